// round 12
// baseline (speedup 1.0000x reference)
#include <cuda_runtime.h>
#include <cuda_bf16.h>
#include <math.h>
#include <cstdint>

// ---------------------------------------------------------------------------
// Problem constants: B=2, L=2048, D=2048, H=16, dk=64, dv=128.  M = B*L = 4096.
// ---------------------------------------------------------------------------
#define MTOK 4096
#define DMODEL 2048
#define DQK 1024
#define NHEAD 16
#define DK 64
#define DV 128
#define SEQ 2048
#define SCALE_K 0.08838834764831845f   // 128^-0.5
#define INV_NORM 0.0625f               // 1/16
#define CH 64                          // scan chunk length
#define NCK (SEQ / CH)                 // 32 chunks per (b,h)
#define BH (2 * NHEAD)                 // 32
#define QS 3072                        // row stride of fused [q|k|kg]
#define VS 4096                        // row stride of fused [v|gp]

#if defined(__CUDA_ARCH__) && (__CUDA_ARCH__ == 1030) && defined(__CUDA_ARCH_FEAT_SM103_ALL)
#define USE_TCGEN05 1
#else
#define USE_TCGEN05 0
#endif

// ---------------------------------------------------------------------------
// Scratch (device globals: no allocation allowed)
// ---------------------------------------------------------------------------
__device__ float g_qkg[MTOK * QS];                // [q | k*scale | kg]
__device__ float g_vg [MTOK * VS];                // [v | gp]
__device__ float g_o  [MTOK * DMODEL];
__device__ float g_a  [BH * SEQ * DK];            // prefix decay products
__device__ float g_U  [BH * NCK * DK * DV];       // per-chunk K̂ᵀV
__device__ float g_Sp [BH * NCK * DK * DV];       // state BEFORE each chunk
__device__ float g_bqkg[QS], g_bvg[VS];           // fused bias vectors

__device__ __nv_bfloat16 g_xh[MTOK * DMODEL],  g_xl[MTOK * DMODEL];
__device__ __nv_bfloat16 g_zh[MTOK * DMODEL],  g_zl[MTOK * DMODEL];
__device__ __nv_bfloat16 g_wqkh[QS * DMODEL],  g_wqkl[QS * DMODEL];
__device__ __nv_bfloat16 g_wvgh[VS * DMODEL],  g_wvgl[VS * DMODEL];
__device__ __nv_bfloat16 g_woh[DMODEL * DMODEL], g_wol[DMODEL * DMODEL];

// ---------------------------------------------------------------------------
// PTX helpers
// ---------------------------------------------------------------------------
__device__ __forceinline__ uint32_t smem_u32(const void* p) {
    uint32_t a;
    asm("{ .reg .u64 t; cvta.to.shared.u64 t, %1; cvt.u32.u64 %0, t; }" : "=r"(a) : "l"(p));
    return a;
}

#define SWZ64(o) ((o) ^ (((o) >> 3) & 0x30))

#define CP_ASYNC16(dst, src) \
    asm volatile("cp.async.cg.shared.global [%0], [%1], 16;" :: "r"(dst), "l"(src))
#define CP_ASYNC_MBAR_ARRIVE(mb) \
    asm volatile("cp.async.mbarrier.arrive.noinc.shared.b64 [%0];" :: "r"((uint32_t)(mb)) : "memory")

#define MBARRIER_INIT(mb, cnt) \
    asm volatile("mbarrier.init.shared.b64 [%0], %1;" :: "r"((uint32_t)(mb)), "r"((uint32_t)(cnt)) : "memory")

#define MBARRIER_WAIT_PARITY(mb, par) do { \
    uint32_t _mb = (uint32_t)(mb); uint32_t _p = (uint32_t)(par); uint32_t _done; \
    asm volatile("{\n\t.reg .pred p;\n\t" \
        "mbarrier.try_wait.parity.acquire.cta.shared::cta.b64 p, [%1], %2;\n\t" \
        "selp.b32 %0, 1, 0, p;\n\t}" : "=r"(_done) : "r"(_mb), "r"(_p) : "memory"); \
    if (!_done) { \
        asm volatile("{\n\t.reg .pred P1;\n\t" \
            "WL_%=:\n\t" \
            "mbarrier.try_wait.parity.acquire.cta.shared::cta.b64 P1, [%0], %1, 0x989680;\n\t" \
            "@P1 bra.uni WD_%=;\n\t" \
            "bra.uni WL_%=;\n\t" \
            "WD_%=:\n\t}" :: "r"(_mb), "r"(_p) : "memory"); \
    } \
} while (0)

#if USE_TCGEN05
__device__ __forceinline__ uint32_t elect_one_pred() {
    uint32_t pred;
    asm volatile("{\n\t.reg .pred p;\n\telect.sync _|p, 0xFFFFFFFF;\n\t"
                 "selp.b32 %0, 1, 0, p;\n\t}" : "=r"(pred));
    return pred;
}

#define TCGEN05_ALLOC(smem_res, ncols) \
    asm volatile("tcgen05.alloc.cta_group::1.sync.aligned.shared::cta.b32 [%0], %1;" \
                 :: "r"((uint32_t)(smem_res)), "r"((uint32_t)(ncols)) : "memory")
#define TCGEN05_DEALLOC(tm, ncols) \
    asm volatile("tcgen05.dealloc.cta_group::1.sync.aligned.b32 %0, %1;" :: "r"(tm), "r"((uint32_t)(ncols)))
#define TCGEN05_RELINQ() \
    asm volatile("tcgen05.relinquish_alloc_permit.cta_group::1.sync.aligned;")
#define TCGEN05_COMMIT(mb) \
    asm volatile("tcgen05.commit.cta_group::1.mbarrier::arrive::one.shared::cluster.b64 [%0];" \
                 :: "r"((uint32_t)(mb)) : "memory")
#define TCGEN05_FENCE_AFTER() \
    asm volatile("tcgen05.fence::after_thread_sync;" ::: "memory")
#define TCGEN05_WAIT_LD() \
    asm volatile("tcgen05.wait::ld.sync.aligned;" ::: "memory")
#define FENCE_PROXY_ASYNC() \
    asm volatile("fence.proxy.async.shared::cta;" ::: "memory")

#define TCGEN05_LD_X32(r, tm) \
    asm volatile("tcgen05.ld.sync.aligned.32x32b.x32.b32 " \
        "{%0, %1, %2, %3, %4, %5, %6, %7, %8, %9, %10, %11, %12, %13, %14, %15, " \
        " %16, %17, %18, %19, %20, %21, %22, %23, %24, %25, %26, %27, %28, %29, %30, %31}, [%32];" \
        : "=r"((r)[0]),  "=r"((r)[1]),  "=r"((r)[2]),  "=r"((r)[3]), \
          "=r"((r)[4]),  "=r"((r)[5]),  "=r"((r)[6]),  "=r"((r)[7]), \
          "=r"((r)[8]),  "=r"((r)[9]),  "=r"((r)[10]), "=r"((r)[11]), \
          "=r"((r)[12]), "=r"((r)[13]), "=r"((r)[14]), "=r"((r)[15]), \
          "=r"((r)[16]), "=r"((r)[17]), "=r"((r)[18]), "=r"((r)[19]), \
          "=r"((r)[20]), "=r"((r)[21]), "=r"((r)[22]), "=r"((r)[23]), \
          "=r"((r)[24]), "=r"((r)[25]), "=r"((r)[26]), "=r"((r)[27]), \
          "=r"((r)[28]), "=r"((r)[29]), "=r"((r)[30]), "=r"((r)[31]) \
        : "r"(tm))

// K-major SW64 descriptor: layout=4 (SW64), version=1, SBO=32, LBO=1
static constexpr uint64_t DESC_BASE_SW64 =
    (uint64_t(4) << 61) | (uint64_t(1) << 46) | (uint64_t(32) << 32) | (uint64_t(1) << 16);
#define MAKE_DESC64(addr) (DESC_BASE_SW64 | ((uint64_t)((addr) >> 4) & 0x3FFF))

__device__ __forceinline__ void mma_f16_ss(uint32_t d, uint64_t ad, uint64_t bd,
                                           uint32_t idesc, uint32_t en) {
    asm volatile("{\n\t.reg .pred p;\n\tsetp.ne.u32 p, %5, 0;\n\t"
        "tcgen05.mma.cta_group::1.kind::f16 [%0], %1, %2, %3, {%4, %4, %4, %4}, p;\n\t}"
        :: "r"(d), "l"(ad), "l"(bd), "r"(idesc), "r"(0u), "r"(en) : "memory");
}
#endif

// ---------------------------------------------------------------------------
// bf16x3 GEMM:  C[M,N] = (A @ B^T) * alpha (+ bias), split hi/lo operands.
// 256x256 output tile, K-chunk 32 (SW64, 64B rows), warp-specialized:
//   threads 0..255 loaders (cp.async), warp 8 = MMA warp.
// Four 128x128 fp32 accumulators in TMEM (512 cols).
// Stage layout: Ah 16K | Al 16K | Bh 16K | Bl 16K = 64KB; two stages.
// ---------------------------------------------------------------------------
#define BUFB 65536
#define GEMM_DSM (2 * BUFB + 1024)
#define GEMM_THREADS 288

__global__ __launch_bounds__(GEMM_THREADS) __cluster_dims__(1, 1, 1)
void gemm3(const __nv_bfloat16* __restrict__ Ah, const __nv_bfloat16* __restrict__ Al,
           const __nv_bfloat16* __restrict__ Bh, const __nv_bfloat16* __restrict__ Bl,
           const float* __restrict__ bias, float* __restrict__ C,
           int N, int K, float alpha)
{
    extern __shared__ char dsm[];

    const int tid = threadIdx.x;
    const int bm = blockIdx.y * 256;
    const int bn = blockIdx.x * 256;

    const uint32_t raw = smem_u32(dsm);
    const uint32_t sbase = (raw + 1023u) & ~1023u;
    char* sgen = dsm + (sbase - raw);

    const int NC = K / 32;

#if USE_TCGEN05
    __shared__ uint32_t s_tmem;
    __shared__ __align__(16) uint64_t s_full[2];
    __shared__ __align__(16) uint64_t s_empty[2];
    const uint32_t full0  = smem_u32(&s_full[0]),  full1  = smem_u32(&s_full[1]);
    const uint32_t empty0 = smem_u32(&s_empty[0]), empty1 = smem_u32(&s_empty[1]);

    if (tid < 32) { TCGEN05_ALLOC(smem_u32(&s_tmem), 512); TCGEN05_RELINQ(); }
    if (tid == 0) {
        MBARRIER_INIT(full0, 256);  MBARRIER_INIT(full1, 256);
        MBARRIER_INIT(empty0, 1);   MBARRIER_INIT(empty1, 1);
    }
    __syncthreads();
    const uint32_t tmem = s_tmem;

    if (tid < 256) {
        // ---------------- loader role: 16 cp.async per chunk ----------------
        const int lr  = tid >> 2;          // 0..63 base row (stride 64)
        const int seg = tid & 3;           // 16B segment within 64B row
        for (int c = 0; c < NC; c++) {
            if (c >= 2)
                MBARRIER_WAIT_PARITY((c & 1) ? empty1 : empty0, ((c - 2) >> 1) & 1);
            const uint32_t bb = sbase + (c & 1) * BUFB;
            const int k0 = c * 32;
#pragma unroll
            for (int t4 = 0; t4 < 4; t4++) {       // Ah, Al, Bh, Bl (256 rows each)
                const __nv_bfloat16* basep = (t4 == 0) ? Ah : (t4 == 1) ? Al
                                           : (t4 == 2) ? Bh : Bl;
                const int rowoff = (t4 < 2) ? bm : bn;
                uint32_t tb = bb + t4 * 16384;
#pragma unroll
                for (int ii = 0; ii < 4; ii++) {
                    int r = lr + ii * 64;
                    const void* src = basep + (size_t)(rowoff + r) * K + k0 + seg * 8;
                    CP_ASYNC16(tb + SWZ64((uint32_t)(r * 64 + seg * 16)), src);
                }
            }
            CP_ASYNC_MBAR_ARRIVE((c & 1) ? full1 : full0);
        }
    } else if (elect_one_pred()) {
        // ---------------- MMA role: 24 MMAs per K32 chunk -------------------
        const uint32_t IDESC = (1u << 4) | (1u << 7) | (1u << 10) | (16u << 17) | (8u << 24);
        for (int c = 0; c < NC; c++) {
            MBARRIER_WAIT_PARITY((c & 1) ? full1 : full0, (c >> 1) & 1);
            FENCE_PROXY_ASYNC();
            const uint32_t ab = sbase + (c & 1) * BUFB;
            const uint64_t dAh = MAKE_DESC64(ab);
            const uint64_t dAl = MAKE_DESC64(ab + 16384);
            const uint64_t dBh = MAKE_DESC64(ab + 32768);
            const uint64_t dBl = MAKE_DESC64(ab + 49152);
            const uint32_t en0 = (c > 0);
            // hi*hi products (init accumulators on very first k-step)
#pragma unroll
            for (int ks = 0; ks < 2; ks++)
#pragma unroll
                for (int mh = 0; mh < 2; mh++)
#pragma unroll
                    for (int nh = 0; nh < 2; nh++)
                        mma_f16_ss(tmem + (mh * 2 + nh) * 128,
                                   dAh + mh * 512 + ks * 2,
                                   dBh + nh * 512 + ks * 2,
                                   IDESC, en0 || (ks > 0));
            // cross products
#pragma unroll
            for (int ks = 0; ks < 2; ks++)
#pragma unroll
                for (int mh = 0; mh < 2; mh++)
#pragma unroll
                    for (int nh = 0; nh < 2; nh++) {
                        uint32_t d = tmem + (mh * 2 + nh) * 128;
                        mma_f16_ss(d, dAh + mh * 512 + ks * 2,
                                      dBl + nh * 512 + ks * 2, IDESC, 1u);
                        mma_f16_ss(d, dAl + mh * 512 + ks * 2,
                                      dBh + nh * 512 + ks * 2, IDESC, 1u);
                    }
            TCGEN05_COMMIT((c & 1) ? empty1 : empty0);
        }
    }

    __syncthreads();
    MBARRIER_WAIT_PARITY(((NC - 1) & 1) ? empty1 : empty0, ((NC - 1) >> 1) & 1);
    TCGEN05_FENCE_AFTER();
    __syncthreads();

    // epilogue: 4 accumulators x 4 slabs of 32 cols
    float* stage = (float*)sgen;
    for (int acc = 0; acc < 4; acc++) {
        const int mh = acc >> 1, nh = acc & 1;
        for (int slab = 0; slab < 4; slab++) {
            if (tid < 128) {
                uint32_t regs[32];
                TCGEN05_LD_X32(regs, tmem + acc * 128 + slab * 32);
                TCGEN05_WAIT_LD();
#pragma unroll
                for (int cc = 0; cc < 32; cc++) stage[tid * 33 + cc] = __uint_as_float(regs[cc]);
            }
            __syncthreads();
            for (int e = tid; e < 4096; e += GEMM_THREADS) {
                int row = e >> 5, col = e & 31;
                float vv = stage[row * 33 + col] * alpha;
                int gcol = bn + nh * 128 + slab * 32 + col;
                if (bias) vv += bias[gcol];
                C[(size_t)(bm + mh * 128 + row) * N + gcol] = vv;
            }
            __syncthreads();
        }
    }
    if (tid < 32) TCGEN05_DEALLOC(tmem, 512);

#else
    // Correct-but-slow scalar fallback for the generic compile pass.
    // Never selected at runtime: the sm_103a image is always present.
    for (int idx = tid; idx < 256 * 256; idx += GEMM_THREADS) {
        int row = idx >> 8, col = idx & 255;
        float accv = 0.f;
        for (int kk = 0; kk < K; kk++) {
            float a = __bfloat162float(Ah[(size_t)(bm + row) * K + kk]) +
                      __bfloat162float(Al[(size_t)(bm + row) * K + kk]);
            float b = __bfloat162float(Bh[(size_t)(bn + col) * K + kk]) +
                      __bfloat162float(Bl[(size_t)(bn + col) * K + kk]);
            accv = fmaf(a, b, accv);
        }
        accv *= alpha;
        if (bias) accv += bias[bn + col];
        C[(size_t)(bm + row) * N + bn + col] = accv;
    }
    (void)sgen; (void)NC;
#endif
}

// ---------------------------------------------------------------------------
// fp32 -> (hi, lo) bf16 split helpers
// ---------------------------------------------------------------------------
__device__ __forceinline__ void split4(const float4 v,
                                       __nv_bfloat16* hi, __nv_bfloat16* lo, int i)
{
    __nv_bfloat16 h0 = __float2bfloat16(v.x), h1 = __float2bfloat16(v.y);
    __nv_bfloat16 h2 = __float2bfloat16(v.z), h3 = __float2bfloat16(v.w);
    __nv_bfloat16 l0 = __float2bfloat16(v.x - __bfloat162float(h0));
    __nv_bfloat16 l1 = __float2bfloat16(v.y - __bfloat162float(h1));
    __nv_bfloat16 l2 = __float2bfloat16(v.z - __bfloat162float(h2));
    __nv_bfloat16 l3 = __float2bfloat16(v.w - __bfloat162float(h3));
    ushort4 ph = { __bfloat16_as_ushort(h0), __bfloat16_as_ushort(h1),
                   __bfloat16_as_ushort(h2), __bfloat16_as_ushort(h3) };
    ushort4 pl = { __bfloat16_as_ushort(l0), __bfloat16_as_ushort(l1),
                   __bfloat16_as_ushort(l2), __bfloat16_as_ushort(l3) };
    ((ushort4*)hi)[i] = ph;
    ((ushort4*)lo)[i] = pl;
}

// x split, 4 float4 per thread (MLP=4).
__global__ __launch_bounds__(256)
void split32(const float* __restrict__ s, __nv_bfloat16* __restrict__ hi,
             __nv_bfloat16* __restrict__ lo)
{
    int base = blockIdx.x * 1024 + threadIdx.x;
    float4 v0 = ((const float4*)s)[base];
    float4 v1 = ((const float4*)s)[base + 256];
    float4 v2 = ((const float4*)s)[base + 512];
    float4 v3 = ((const float4*)s)[base + 768];
    split4(v0, hi, lo, base);
    split4(v1, hi, lo, base + 256);
    split4(v2, hi, lo, base + 512);
    split4(v3, hi, lo, base + 768);
}

// Weight splits into FUSED layouts. 4 float4/thread. 4096 blocks.
__global__ __launch_bounds__(256)
void split_w(const float* __restrict__ Wq, const float* __restrict__ Wk,
             const float* __restrict__ Wv, const float* __restrict__ Wg,
             const float* __restrict__ Wo,
             __nv_bfloat16* __restrict__ wqkh, __nv_bfloat16* __restrict__ wqkl,
             __nv_bfloat16* __restrict__ wvgh, __nv_bfloat16* __restrict__ wvgl,
             __nv_bfloat16* __restrict__ woh,  __nv_bfloat16* __restrict__ wol)
{
    int b = blockIdx.x;
    const float* src; __nv_bfloat16 *hi, *lo; int dsto; float scale = 1.f;
    if      (b < 512)  { src = Wq; hi = wqkh; lo = wqkl; dsto = 0; }
    else if (b < 1024) { src = Wk; hi = wqkh; lo = wqkl; dsto = 1024 * 512; b -= 512; scale = SCALE_K; }
    else if (b < 2048) { src = Wv; hi = wvgh; lo = wvgl; dsto = 0; b -= 1024; }
    else if (b < 3072) { src = Wg; hi = wvgh; lo = wvgl; dsto = 2048 * 512; b -= 2048; }
    else               { src = Wo; hi = woh;  lo = wol;  dsto = 0; b -= 3072; }
    int base = b * 1024 + threadIdx.x;
#pragma unroll
    for (int u = 0; u < 4; u++) {
        int i = base + u * 256;
        float4 v = ((const float4*)src)[i];
        v.x *= scale; v.y *= scale; v.z *= scale; v.w *= scale;
        split4(v, hi, lo, dsto + i);
    }
}

// W_eff = Wkg2 @ Wkg1 -> wqk rows 2048..3071 (fused), hi/lo split.
__global__ __launch_bounds__(256)
void weff_split(const float* __restrict__ W1, const float* __restrict__ W2,
                __nv_bfloat16* __restrict__ wqkh, __nv_bfloat16* __restrict__ wqkl)
{
    __shared__ __align__(16) float s1[16][128];
    const int tid = threadIdx.x;
    const int d0  = blockIdx.x * 128;
    const int n0  = blockIdx.y * 256;

#pragma unroll
    for (int it = 0; it < 2; it++) {
        int i = it * 256 + tid;
        int r = i >> 5, c4 = i & 31;
        *(float4*)&s1[r][c4 * 4] = *(const float4*)(W1 + r * DMODEL + d0 + c4 * 4);
    }
    __syncthreads();

    const int d4 = tid & 31;
    const int nb = tid >> 5;
    for (int n = n0 + nb; n < n0 + 256; n += 8) {
        const float4 w2a = *(const float4*)(W2 + n * 16);
        const float4 w2b = *(const float4*)(W2 + n * 16 + 4);
        const float4 w2c = *(const float4*)(W2 + n * 16 + 8);
        const float4 w2d = *(const float4*)(W2 + n * 16 + 12);
        float w2[16] = { w2a.x, w2a.y, w2a.z, w2a.w, w2b.x, w2b.y, w2b.z, w2b.w,
                         w2c.x, w2c.y, w2c.z, w2c.w, w2d.x, w2d.y, w2d.z, w2d.w };
        float4 acc = {0.f, 0.f, 0.f, 0.f};
#pragma unroll
        for (int r = 0; r < 16; r++) {
            float4 v = *(const float4*)&s1[r][d4 * 4];
            acc.x = fmaf(w2[r], v.x, acc.x);
            acc.y = fmaf(w2[r], v.y, acc.y);
            acc.z = fmaf(w2[r], v.z, acc.z);
            acc.w = fmaf(w2[r], v.w, acc.w);
        }
        split4(acc, wqkh, wqkl, (2048 + n) * 512 + (d0 >> 2) + d4);
    }
}

// fused bias vectors: bqkg = [0 | 0 | bkg2], bvg = [0 | bg]
__global__ void fill_bias(const float* __restrict__ bkg2, const float* __restrict__ bg,
                          float* __restrict__ bqkg, float* __restrict__ bvg)
{
    int i = blockIdx.x * 256 + threadIdx.x;
    if (i < QS) bqkg[i] = (i >= 2048) ? bkg2[i - 2048] : 0.f;
    if (i < VS) bvg [i] = (i >= 2048) ? bg  [i - 2048] : 0.f;
}

// ===========================================================================
// CHUNKED GLA SCAN (exact algebra; fp32).  Chunk length CH=64.
// ===========================================================================

// ---------- Phase A ----------------------------------------------------------
#define PHA_SMEM (16384 * 4)
__global__ __launch_bounds__(256)
void gla_pha(const float* __restrict__ k, const float* __restrict__ kg,
             const float* __restrict__ v, float* __restrict__ a_g,
             float* __restrict__ U_g)
{
    extern __shared__ float sa[];
    float* lam = sa;                 // [64][64]
    float* kh  = sa + 4096;          // [64][64]
    float* vsm = sa + 8192;          // [64][128]

    const int blk = blockIdx.x;
    const int c   = blk & (NCK - 1);
    const int bh  = blk >> 5;
    const int b   = bh >> 4, h = bh & 15;
    const int t0  = c * CH;
    const int tid = threadIdx.x;

    const float* kb = k  + (size_t)b * SEQ * QS + h * DK;
    const float* gb = kg + (size_t)b * SEQ * QS + h * DK;
    const float* vb = v  + (size_t)b * SEQ * VS + h * DV;
    float* ag = a_g + ((size_t)bh * SEQ + t0) * DK;
    float* Ug = U_g + (size_t)blk * (DK * DV);

    for (int e = tid; e < CH * DK; e += 256) {
        int t = e >> 6, i = e & 63;
        float x = gb[(size_t)(t0 + t) * QS + i];
        float ls = fminf(x, 0.f) - log1pf(__expf(-fabsf(x)));
        lam[t * DK + i] = __expf(ls * INV_NORM);
    }
    for (int e = tid; e < CH * (DV / 4); e += 256) {
        int t = e >> 5, j4 = e & 31;
        *(float4*)&vsm[t * DV + j4 * 4] =
            *(const float4*)&vb[(size_t)(t0 + t) * VS + j4 * 4];
    }
    __syncthreads();

    if (tid < DK) {
        const int i = tid;
        float acc = 1.f;
        for (int t = 0; t < CH; t++) {
            acc *= lam[t * DK + i];
            ag[(size_t)t * DK + i] = acc;
        }
        float w = 1.f;
        for (int t = CH - 1; t >= 0; t--) {
            kh[t * DK + i] = kb[(size_t)(t0 + t) * QS + i] * w;
            w *= lam[t * DK + i];
        }
    }
    __syncthreads();

    {
        const int i0 = (tid >> 5) * 8;
        const int j0 = (tid & 31) * 4;
        float acc[8][4];
#pragma unroll
        for (int ii = 0; ii < 8; ii++)
#pragma unroll
            for (int jj = 0; jj < 4; jj++) acc[ii][jj] = 0.f;

        for (int s = 0; s < CH; s++) {
            float4 va = *(const float4*)&vsm[s * DV + j0];
            float kv[8];
            *(float4*)&kv[0] = *(const float4*)&kh[s * DK + i0];
            *(float4*)&kv[4] = *(const float4*)&kh[s * DK + i0 + 4];
#pragma unroll
            for (int ii = 0; ii < 8; ii++) {
                acc[ii][0] = fmaf(kv[ii], va.x, acc[ii][0]);
                acc[ii][1] = fmaf(kv[ii], va.y, acc[ii][1]);
                acc[ii][2] = fmaf(kv[ii], va.z, acc[ii][2]);
                acc[ii][3] = fmaf(kv[ii], va.w, acc[ii][3]);
            }
        }
#pragma unroll
        for (int ii = 0; ii < 8; ii++) {
            float4 w4 = { acc[ii][0], acc[ii][1], acc[ii][2], acc[ii][3] };
            *(float4*)&Ug[(size_t)(i0 + ii) * DV + j0] = w4;
        }
    }
}

// ---------- Phase B ----------------------------------------------------------
__global__ __launch_bounds__(256)
void gla_phb(const float* __restrict__ a_g, const float* __restrict__ U_g,
             float* __restrict__ Sp_g)
{
    const int bh  = blockIdx.x;
    const int tid = threadIdx.x;
    float S[32];
#pragma unroll
    for (int w = 0; w < 32; w++) S[w] = 0.f;

    for (int c = 0; c < NCK; c++) {
        const float* Ug = U_g + ((size_t)bh * NCK + c) * (DK * DV);
        float* Sg = Sp_g + ((size_t)bh * NCK + c) * (DK * DV);
        const float* a64 = a_g + ((size_t)bh * SEQ + c * CH + CH - 1) * DK;
#pragma unroll
        for (int w = 0; w < 8; w++) {
            int f4 = tid + w * 256;
            int i = f4 >> 5;
            float ai = a64[i];
            float4 u = ((const float4*)Ug)[f4];
            float4 s = *(float4*)&S[w * 4];
            ((float4*)Sg)[f4] = s;
            s.x = fmaf(s.x, ai, u.x);
            s.y = fmaf(s.y, ai, u.y);
            s.z = fmaf(s.z, ai, u.z);
            s.w = fmaf(s.w, ai, u.w);
            *(float4*)&S[w * 4] = s;
        }
    }
}

// ---------- Phase C (register-tiled) -----------------------------------------
#define PHC_SMEM (29248 * 4)
__global__ __launch_bounds__(256)
void gla_phc(const float* __restrict__ q, const float* __restrict__ a_g,
             const float* __restrict__ k, const float* __restrict__ Sp_g,
             const float* __restrict__ v, float* __restrict__ o)
{
    extern __shared__ float sc[];
    float* qt  = sc;            // [64][68]
    float* kT  = sc + 4352;     // [64(i)][68(s)]
    float* Am  = sc + 8704;     // [64][65]
    float* vsm = sc + 12864;    // [64][128]
    float* Ssm = sc + 21056;    // [64][128]

    const int blk = blockIdx.x;
    const int c   = blk & (NCK - 1);
    const int bh  = blk >> 5;
    const int b   = bh >> 4, h = bh & 15;
    const int t0  = c * CH;
    const int tid = threadIdx.x;

    const float* qb = q + (size_t)b * SEQ * QS + h * DK;
    const float* kb = k + (size_t)b * SEQ * QS + h * DK;
    const float* vb = v + (size_t)b * SEQ * VS + h * DV;
    const float* ag = a_g + ((size_t)bh * SEQ + t0) * DK;
    const float* Sg = Sp_g + (size_t)blk * (DK * DV);
    float* ob = o + (size_t)b * SEQ * DMODEL + h * DV;

    for (int e = tid; e < CH * DK; e += 256) {
        int t = e >> 6, i = e & 63;
        float aa = ag[(size_t)t * DK + i];
        qt[t * 68 + i] = qb[(size_t)(t0 + t) * QS + i] * aa;
        kT[i * 68 + t] = kb[(size_t)(t0 + t) * QS + i] / aa;
    }
    for (int e = tid; e < CH * (DV / 4); e += 256) {
        int t = e >> 5, j4 = e & 31;
        *(float4*)&vsm[t * DV + j4 * 4] =
            *(const float4*)&vb[(size_t)(t0 + t) * VS + j4 * 4];
        *(float4*)&Ssm[t * DV + j4 * 4] = ((const float4*)Sg)[e];
    }
    __syncthreads();

    // A = tril(qt @ kT): thread owns 2 t x 8 s
    {
        const int ta = (tid >> 3) * 2;
        const int s0 = (tid & 7) * 8;
        float acc0[8], acc1[8];
#pragma unroll
        for (int ss = 0; ss < 8; ss++) { acc0[ss] = 0.f; acc1[ss] = 0.f; }
        for (int i = 0; i < DK; i++) {
            float q0 = qt[ta * 68 + i];
            float q1 = qt[(ta + 1) * 68 + i];
            const float* kr = &kT[i * 68 + s0];
            float4 k0 = *(const float4*)&kr[0];
            float4 k1 = *(const float4*)&kr[4];
            float kv[8] = { k0.x, k0.y, k0.z, k0.w, k1.x, k1.y, k1.z, k1.w };
#pragma unroll
            for (int ss = 0; ss < 8; ss++) {
                acc0[ss] = fmaf(q0, kv[ss], acc0[ss]);
                acc1[ss] = fmaf(q1, kv[ss], acc1[ss]);
            }
        }
#pragma unroll
        for (int ss = 0; ss < 8; ss++) {
            int s = s0 + ss;
            Am[ta * 65 + s]       = (s <= ta)     ? acc0[ss] : 0.f;
            Am[(ta + 1) * 65 + s] = (s <= ta + 1) ? acc1[ss] : 0.f;
        }
    }
    __syncthreads();

    // o = A@V + qt@S_pre : thread owns 4 t x 8 j
    {
        const int to = (tid >> 4) * 4;
        const int j0 = (tid & 15) * 8;
        float acc[4][8];
#pragma unroll
        for (int r = 0; r < 4; r++)
#pragma unroll
            for (int jj = 0; jj < 8; jj++) acc[r][jj] = 0.f;

        const int smax = to + 4;
        for (int s = 0; s < smax; s++) {
            float a0 = Am[to * 65 + s];
            float a1 = Am[(to + 1) * 65 + s];
            float a2 = Am[(to + 2) * 65 + s];
            float a3 = Am[(to + 3) * 65 + s];
            const float* vr = &vsm[s * DV + j0];
            float4 v0 = *(const float4*)&vr[0];
            float4 v1 = *(const float4*)&vr[4];
            float vv[8] = { v0.x, v0.y, v0.z, v0.w, v1.x, v1.y, v1.z, v1.w };
#pragma unroll
            for (int jj = 0; jj < 8; jj++) {
                acc[0][jj] = fmaf(a0, vv[jj], acc[0][jj]);
                acc[1][jj] = fmaf(a1, vv[jj], acc[1][jj]);
                acc[2][jj] = fmaf(a2, vv[jj], acc[2][jj]);
                acc[3][jj] = fmaf(a3, vv[jj], acc[3][jj]);
            }
        }
        for (int i = 0; i < DK; i++) {
            float q0 = qt[to * 68 + i];
            float q1 = qt[(to + 1) * 68 + i];
            float q2 = qt[(to + 2) * 68 + i];
            float q3 = qt[(to + 3) * 68 + i];
            const float* sr = &Ssm[i * DV + j0];
            float4 s0v = *(const float4*)&sr[0];
            float4 s1v = *(const float4*)&sr[4];
            float sv[8] = { s0v.x, s0v.y, s0v.z, s0v.w, s1v.x, s1v.y, s1v.z, s1v.w };
#pragma unroll
            for (int jj = 0; jj < 8; jj++) {
                acc[0][jj] = fmaf(q0, sv[jj], acc[0][jj]);
                acc[1][jj] = fmaf(q1, sv[jj], acc[1][jj]);
                acc[2][jj] = fmaf(q2, sv[jj], acc[2][jj]);
                acc[3][jj] = fmaf(q3, sv[jj], acc[3][jj]);
            }
        }
#pragma unroll
        for (int r = 0; r < 4; r++) {
            float* orow = ob + (size_t)(t0 + to + r) * DMODEL + j0;
            float4 w0 = { acc[r][0], acc[r][1], acc[r][2], acc[r][3] };
            float4 w1 = { acc[r][4], acc[r][5], acc[r][6], acc[r][7] };
            *(float4*)&orow[0] = w0;
            *(float4*)&orow[4] = w1;
        }
    }
}

// ---------------------------------------------------------------------------
// LayerNorm(dv=128, no affine) + SiLU(gp) gate, fused hi/lo bf16 split.
// ---------------------------------------------------------------------------
__global__ __launch_bounds__(256)
void ln_gate(const float* __restrict__ o, const float* __restrict__ gp,
             __nv_bfloat16* __restrict__ zh, __nv_bfloat16* __restrict__ zl)
{
    int gw   = (blockIdx.x * blockDim.x + threadIdx.x) >> 5;   // 65536 rows
    int lane = threadIdx.x & 31;
    int m = gw >> 4, h = gw & 15;

    float4 ov = ((const float4*)(o + (size_t)gw * 128))[lane];
    float s = ov.x + ov.y + ov.z + ov.w;
#pragma unroll
    for (int d = 16; d > 0; d >>= 1) s += __shfl_xor_sync(0xffffffffu, s, d);
    float mu = s * (1.f / 128.f);

    float dx0 = ov.x - mu, dx1 = ov.y - mu, dx2 = ov.z - mu, dx3 = ov.w - mu;
    float vsum = dx0 * dx0 + dx1 * dx1 + dx2 * dx2 + dx3 * dx3;
#pragma unroll
    for (int d = 16; d > 0; d >>= 1) vsum += __shfl_xor_sync(0xffffffffu, vsum, d);
    float inv = rsqrtf(vsum * (1.f / 128.f) + 1e-5f);

    float4 gv = ((const float4*)(gp + (size_t)m * VS + (h << 7)))[lane];
    float4 z;
    z.x = (gv.x / (1.f + __expf(-gv.x))) * (dx0 * inv);
    z.y = (gv.y / (1.f + __expf(-gv.y))) * (dx1 * inv);
    z.z = (gv.z / (1.f + __expf(-gv.z))) * (dx2 * inv);
    z.w = (gv.w / (1.f + __expf(-gv.w))) * (dx3 * inv);
    split4(z, zh, zl, gw * 32 + lane);
}

// ---------------------------------------------------------------------------
extern "C" void kernel_launch(void* const* d_in, const int* in_sizes, int n_in,
                              void* d_out, int out_size)
{
    const float* x    = (const float*)d_in[0];
    const float* Wq   = (const float*)d_in[1];
    const float* Wk   = (const float*)d_in[2];
    const float* Wkg1 = (const float*)d_in[3];
    const float* Wkg2 = (const float*)d_in[4];
    const float* bkg2 = (const float*)d_in[5];
    const float* Wv   = (const float*)d_in[6];
    const float* Wg   = (const float*)d_in[7];
    const float* bg   = (const float*)d_in[8];
    const float* Wo   = (const float*)d_in[9];
    float* out = (float*)d_out;

    float *qkg, *vg, *o, *ad, *Ud, *Sp, *bqkg, *bvg;
    cudaGetSymbolAddress((void**)&qkg,  g_qkg);
    cudaGetSymbolAddress((void**)&vg,   g_vg);
    cudaGetSymbolAddress((void**)&o,    g_o);
    cudaGetSymbolAddress((void**)&ad,   g_a);
    cudaGetSymbolAddress((void**)&Ud,   g_U);
    cudaGetSymbolAddress((void**)&Sp,   g_Sp);
    cudaGetSymbolAddress((void**)&bqkg, g_bqkg);
    cudaGetSymbolAddress((void**)&bvg,  g_bvg);

    __nv_bfloat16 *xh, *xl, *zh, *zl;
    __nv_bfloat16 *wqkh, *wqkl, *wvgh, *wvgl, *woh, *wol;
    cudaGetSymbolAddress((void**)&xh,   g_xh);   cudaGetSymbolAddress((void**)&xl,   g_xl);
    cudaGetSymbolAddress((void**)&zh,   g_zh);   cudaGetSymbolAddress((void**)&zl,   g_zl);
    cudaGetSymbolAddress((void**)&wqkh, g_wqkh); cudaGetSymbolAddress((void**)&wqkl, g_wqkl);
    cudaGetSymbolAddress((void**)&wvgh, g_wvgh); cudaGetSymbolAddress((void**)&wvgl, g_wvgl);
    cudaGetSymbolAddress((void**)&woh,  g_woh);  cudaGetSymbolAddress((void**)&wol,  g_wol);

    cudaFuncSetAttribute(gemm3, cudaFuncAttributeMaxDynamicSharedMemorySize, GEMM_DSM);
    cudaFuncSetAttribute(gla_pha, cudaFuncAttributeMaxDynamicSharedMemorySize, PHA_SMEM);
    cudaFuncSetAttribute(gla_phc, cudaFuncAttributeMaxDynamicSharedMemorySize, PHC_SMEM);

    // splits + fused low-rank weight + fused biases
    split32<<<(MTOK * DMODEL) / 4096, 256>>>(x, xh, xl);
    split_w<<<4096, 256>>>(Wq, Wk, Wv, Wg, Wo, wqkh, wqkl, wvgh, wvgl, woh, wol);
    weff_split<<<dim3(16, 4), 256>>>(Wkg1, Wkg2, wqkh, wqkl);
    fill_bias<<<16, 256>>>(bkg2, bg, bqkg, bvg);

    dim3 blk(GEMM_THREADS);
    dim3 gQKG(QS / 256, MTOK / 256);     // 12 x 16
    dim3 gVG (VS / 256, MTOK / 256);     // 16 x 16
    dim3 gOUT(DMODEL / 256, MTOK / 256); // 8 x 16

    gemm3<<<gQKG, blk, GEMM_DSM>>>(xh, xl, wqkh, wqkl, bqkg, qkg, QS, DMODEL, 1.f);
    gemm3<<<gVG,  blk, GEMM_DSM>>>(xh, xl, wvgh, wvgl, bvg,  vg,  VS, DMODEL, 1.f);

    // chunked scan (q = qkg+0, k = qkg+1024, kg = qkg+2048; v = vg+0)
    gla_pha<<<BH * NCK, 256, PHA_SMEM>>>(qkg + 1024, qkg + 2048, vg, ad, Ud);
    gla_phb<<<BH, 256>>>(ad, Ud, Sp);
    gla_phc<<<BH * NCK, 256, PHC_SMEM>>>(qkg, ad, qkg + 1024, Sp, vg, o);

    ln_gate<<<(MTOK * NHEAD * 32) / 256, 256>>>(o, vg + 2048, zh, zl);

    gemm3<<<gOUT, blk, GEMM_DSM>>>(zh, zl, woh, wol, nullptr, out, DMODEL, DMODEL, 1.f);
}

// round 13
// speedup vs baseline: 1.1285x; 1.1285x over previous
#include <cuda_runtime.h>
#include <cuda_bf16.h>
#include <math.h>
#include <cstdint>

// ---------------------------------------------------------------------------
// Problem constants: B=2, L=2048, D=2048, H=16, dk=64, dv=128.  M = B*L = 4096.
// ---------------------------------------------------------------------------
#define MTOK 4096
#define DMODEL 2048
#define DQK 1024
#define NHEAD 16
#define DK 64
#define DV 128
#define SEQ 2048
#define SCALE_K 0.08838834764831845f   // 128^-0.5
#define INV_NORM 0.0625f               // 1/16
#define CH 64                          // scan chunk length
#define NCK (SEQ / CH)                 // 32 chunks per (b,h)
#define BH (2 * NHEAD)                 // 32
#define PS 7168                        // row stride of fused [q|k|kg|v|gp]

#if defined(__CUDA_ARCH__) && (__CUDA_ARCH__ == 1030) && defined(__CUDA_ARCH_FEAT_SM103_ALL)
#define USE_TCGEN05 1
#else
#define USE_TCGEN05 0
#endif

// ---------------------------------------------------------------------------
// Scratch (device globals: no allocation allowed)
// ---------------------------------------------------------------------------
__device__ float g_proj[MTOK * PS];               // [q | k*s | kg | v | gp]
__device__ float g_o  [MTOK * DMODEL];
__device__ float g_a  [BH * SEQ * DK];            // prefix decay products
__device__ float g_U  [BH * NCK * DK * DV];       // per-chunk K̂ᵀV
__device__ float g_Sp [BH * NCK * DK * DV];       // state BEFORE each chunk
__device__ float g_ball[PS];                      // fused bias vector

__device__ __nv_bfloat16 g_xh[MTOK * DMODEL],  g_xl[MTOK * DMODEL];
__device__ __nv_bfloat16 g_zh[MTOK * DMODEL],  g_zl[MTOK * DMODEL];
__device__ __nv_bfloat16 g_wallh[PS * DMODEL], g_walll[PS * DMODEL];
__device__ __nv_bfloat16 g_woh[DMODEL * DMODEL], g_wol[DMODEL * DMODEL];

// ---------------------------------------------------------------------------
// PTX helpers
// ---------------------------------------------------------------------------
__device__ __forceinline__ uint32_t smem_u32(const void* p) {
    uint32_t a;
    asm("{ .reg .u64 t; cvta.to.shared.u64 t, %1; cvt.u32.u64 %0, t; }" : "=r"(a) : "l"(p));
    return a;
}

#define SWZ(o) ((o) ^ (((o) >> 3) & 0x70))

#define CP_ASYNC16(dst, src) \
    asm volatile("cp.async.cg.shared.global [%0], [%1], 16;" :: "r"(dst), "l"(src))
#define CP_ASYNC_MBAR_ARRIVE(mb) \
    asm volatile("cp.async.mbarrier.arrive.noinc.shared.b64 [%0];" :: "r"((uint32_t)(mb)) : "memory")

#define MBARRIER_INIT(mb, cnt) \
    asm volatile("mbarrier.init.shared.b64 [%0], %1;" :: "r"((uint32_t)(mb)), "r"((uint32_t)(cnt)) : "memory")

#define MBARRIER_WAIT_PARITY(mb, par) do { \
    uint32_t _mb = (uint32_t)(mb); uint32_t _p = (uint32_t)(par); uint32_t _done; \
    asm volatile("{\n\t.reg .pred p;\n\t" \
        "mbarrier.try_wait.parity.acquire.cta.shared::cta.b64 p, [%1], %2;\n\t" \
        "selp.b32 %0, 1, 0, p;\n\t}" : "=r"(_done) : "r"(_mb), "r"(_p) : "memory"); \
    if (!_done) { \
        asm volatile("{\n\t.reg .pred P1;\n\t" \
            "WL_%=:\n\t" \
            "mbarrier.try_wait.parity.acquire.cta.shared::cta.b64 P1, [%0], %1, 0x989680;\n\t" \
            "@P1 bra.uni WD_%=;\n\t" \
            "bra.uni WL_%=;\n\t" \
            "WD_%=:\n\t}" :: "r"(_mb), "r"(_p) : "memory"); \
    } \
} while (0)

#if USE_TCGEN05
__device__ __forceinline__ uint32_t elect_one_pred() {
    uint32_t pred;
    asm volatile("{\n\t.reg .pred p;\n\telect.sync _|p, 0xFFFFFFFF;\n\t"
                 "selp.b32 %0, 1, 0, p;\n\t}" : "=r"(pred));
    return pred;
}

#define TCGEN05_ALLOC(smem_res, ncols) \
    asm volatile("tcgen05.alloc.cta_group::1.sync.aligned.shared::cta.b32 [%0], %1;" \
                 :: "r"((uint32_t)(smem_res)), "r"((uint32_t)(ncols)) : "memory")
#define TCGEN05_DEALLOC(tm, ncols) \
    asm volatile("tcgen05.dealloc.cta_group::1.sync.aligned.b32 %0, %1;" :: "r"(tm), "r"((uint32_t)(ncols)))
#define TCGEN05_RELINQ() \
    asm volatile("tcgen05.relinquish_alloc_permit.cta_group::1.sync.aligned;")
#define TCGEN05_COMMIT(mb) \
    asm volatile("tcgen05.commit.cta_group::1.mbarrier::arrive::one.shared::cluster.b64 [%0];" \
                 :: "r"((uint32_t)(mb)) : "memory")
#define TCGEN05_FENCE_AFTER() \
    asm volatile("tcgen05.fence::after_thread_sync;" ::: "memory")
#define TCGEN05_WAIT_LD() \
    asm volatile("tcgen05.wait::ld.sync.aligned;" ::: "memory")
#define FENCE_PROXY_ASYNC() \
    asm volatile("fence.proxy.async.shared::cta;" ::: "memory")

#define TCGEN05_LD_X32(r, tm) \
    asm volatile("tcgen05.ld.sync.aligned.32x32b.x32.b32 " \
        "{%0, %1, %2, %3, %4, %5, %6, %7, %8, %9, %10, %11, %12, %13, %14, %15, " \
        " %16, %17, %18, %19, %20, %21, %22, %23, %24, %25, %26, %27, %28, %29, %30, %31}, [%32];" \
        : "=r"((r)[0]),  "=r"((r)[1]),  "=r"((r)[2]),  "=r"((r)[3]), \
          "=r"((r)[4]),  "=r"((r)[5]),  "=r"((r)[6]),  "=r"((r)[7]), \
          "=r"((r)[8]),  "=r"((r)[9]),  "=r"((r)[10]), "=r"((r)[11]), \
          "=r"((r)[12]), "=r"((r)[13]), "=r"((r)[14]), "=r"((r)[15]), \
          "=r"((r)[16]), "=r"((r)[17]), "=r"((r)[18]), "=r"((r)[19]), \
          "=r"((r)[20]), "=r"((r)[21]), "=r"((r)[22]), "=r"((r)[23]), \
          "=r"((r)[24]), "=r"((r)[25]), "=r"((r)[26]), "=r"((r)[27]), \
          "=r"((r)[28]), "=r"((r)[29]), "=r"((r)[30]), "=r"((r)[31]) \
        : "r"(tm))

static constexpr uint64_t DESC_BASE_SW128 =
    (uint64_t(2) << 61) | (uint64_t(1) << 46) | (uint64_t(64) << 32) | (uint64_t(1) << 16);
#define MAKE_DESC(addr) (DESC_BASE_SW128 | ((uint64_t)((addr) >> 4) & 0x3FFF))

__device__ __forceinline__ void mma_f16_ss(uint32_t d, uint64_t ad, uint64_t bd,
                                           uint32_t idesc, uint32_t en) {
    asm volatile("{\n\t.reg .pred p;\n\tsetp.ne.u32 p, %5, 0;\n\t"
        "tcgen05.mma.cta_group::1.kind::f16 [%0], %1, %2, %3, {%4, %4, %4, %4}, p;\n\t}"
        :: "r"(d), "l"(ad), "l"(bd), "r"(idesc), "r"(0u), "r"(en) : "memory");
}
#else
__device__ __forceinline__ void mma16816(float* d, const uint32_t* a, const uint32_t* b) {
    asm volatile("mma.sync.aligned.m16n8k16.row.col.f32.bf16.bf16.f32 "
        "{%0,%1,%2,%3}, {%4,%5,%6,%7}, {%8,%9}, {%0,%1,%2,%3};"
        : "+f"(d[0]), "+f"(d[1]), "+f"(d[2]), "+f"(d[3])
        : "r"(a[0]), "r"(a[1]), "r"(a[2]), "r"(a[3]), "r"(b[0]), "r"(b[1]));
}
#endif

// ---------------------------------------------------------------------------
// bf16x3 GEMM:  C[M,N] = (A @ B^T) * alpha (+ bias), split hi/lo operands.
// Tile 128x256 (two N=128 MMA halves), K-chunk 64 (SW128), warp-specialized:
//   threads 0..255 loaders (cp.async + noinc mbarrier arrive), warp 8 = MMA.
// Stage: Ah 16K | Al 16K | Bh 32K | Bl 32K = 96KB; two stages.
// ---------------------------------------------------------------------------
#define BUFB 98304
#define GEMM_DSM (2 * BUFB + 1024)
#define GEMM_THREADS 288

__global__ __launch_bounds__(GEMM_THREADS) __cluster_dims__(1, 1, 1)
void gemm3(const __nv_bfloat16* __restrict__ Ah, const __nv_bfloat16* __restrict__ Al,
           const __nv_bfloat16* __restrict__ Bh, const __nv_bfloat16* __restrict__ Bl,
           const float* __restrict__ bias, float* __restrict__ C,
           int N, int K, float alpha)
{
    extern __shared__ char dsm[];

    const int tid = threadIdx.x;
    const int bm = blockIdx.y * 128;
    const int bn = blockIdx.x * 256;

    const uint32_t raw = smem_u32(dsm);
    const uint32_t sbase = (raw + 1023u) & ~1023u;
    char* sgen = dsm + (sbase - raw);

    const int NC = K / 64;

#if USE_TCGEN05
    __shared__ uint32_t s_tmem;
    __shared__ __align__(16) uint64_t s_full[2];
    __shared__ __align__(16) uint64_t s_empty[2];
    const uint32_t full0  = smem_u32(&s_full[0]),  full1  = smem_u32(&s_full[1]);
    const uint32_t empty0 = smem_u32(&s_empty[0]), empty1 = smem_u32(&s_empty[1]);

    if (tid < 32) { TCGEN05_ALLOC(smem_u32(&s_tmem), 256); TCGEN05_RELINQ(); }
    if (tid == 0) {
        MBARRIER_INIT(full0, 256);  MBARRIER_INIT(full1, 256);
        MBARRIER_INIT(empty0, 1);   MBARRIER_INIT(empty1, 1);
    }
    __syncthreads();
    const uint32_t tmem = s_tmem;

    if (tid < 256) {
        const int lr  = tid >> 3;
        const int seg = tid & 7;
        for (int c = 0; c < NC; c++) {
            if (c >= 2)
                MBARRIER_WAIT_PARITY((c & 1) ? empty1 : empty0, ((c - 2) >> 1) & 1);
            const uint32_t bb = sbase + (c & 1) * BUFB;
            const int k0 = c * 64;
#pragma unroll
            for (int t2 = 0; t2 < 2; t2++) {
                const __nv_bfloat16* basep = t2 ? Al : Ah;
                uint32_t tb = bb + t2 * 16384;
#pragma unroll
                for (int ii = 0; ii < 4; ii++) {
                    int r = lr + ii * 32;
                    const void* src = basep + (size_t)(bm + r) * K + k0 + seg * 8;
                    CP_ASYNC16(tb + SWZ((uint32_t)(r * 128 + seg * 16)), src);
                }
            }
#pragma unroll
            for (int t2 = 0; t2 < 2; t2++) {
                const __nv_bfloat16* basep = t2 ? Bl : Bh;
                uint32_t tb = bb + 32768 + t2 * 32768;
#pragma unroll
                for (int ii = 0; ii < 8; ii++) {
                    int r = lr + ii * 32;
                    const void* src = basep + (size_t)(bn + r) * K + k0 + seg * 8;
                    CP_ASYNC16(tb + SWZ((uint32_t)(r * 128 + seg * 16)), src);
                }
            }
            CP_ASYNC_MBAR_ARRIVE((c & 1) ? full1 : full0);
        }
    } else if (elect_one_pred()) {
        const uint32_t IDESC = (1u << 4) | (1u << 7) | (1u << 10) | (16u << 17) | (8u << 24);
        for (int c = 0; c < NC; c++) {
            MBARRIER_WAIT_PARITY((c & 1) ? full1 : full0, (c >> 1) & 1);
            FENCE_PROXY_ASYNC();
            const uint32_t ab = sbase + (c & 1) * BUFB;
            const uint64_t dAh  = MAKE_DESC(ab);
            const uint64_t dAl  = MAKE_DESC(ab + 16384);
            const uint64_t dBh0 = MAKE_DESC(ab + 32768);
            const uint64_t dBh1 = MAKE_DESC(ab + 32768 + 16384);
            const uint64_t dBl0 = MAKE_DESC(ab + 65536);
            const uint64_t dBl1 = MAKE_DESC(ab + 65536 + 16384);
            const uint32_t en0 = (c > 0);
#pragma unroll
            for (int ks = 0; ks < 4; ks++)
                mma_f16_ss(tmem,       dAh + ks * 2, dBh0 + ks * 2, IDESC, en0 || (ks > 0));
#pragma unroll
            for (int ks = 0; ks < 4; ks++)
                mma_f16_ss(tmem + 128, dAh + ks * 2, dBh1 + ks * 2, IDESC, en0 || (ks > 0));
#pragma unroll
            for (int ks = 0; ks < 4; ks++) {
                mma_f16_ss(tmem,       dAh + ks * 2, dBl0 + ks * 2, IDESC, 1u);
                mma_f16_ss(tmem + 128, dAh + ks * 2, dBl1 + ks * 2, IDESC, 1u);
                mma_f16_ss(tmem,       dAl + ks * 2, dBh0 + ks * 2, IDESC, 1u);
                mma_f16_ss(tmem + 128, dAl + ks * 2, dBh1 + ks * 2, IDESC, 1u);
            }
            TCGEN05_COMMIT((c & 1) ? empty1 : empty0);
        }
    }

    __syncthreads();
    MBARRIER_WAIT_PARITY(((NC - 1) & 1) ? empty1 : empty0, ((NC - 1) >> 1) & 1);
    TCGEN05_FENCE_AFTER();
    __syncthreads();

    float* stage = (float*)sgen;
    for (int slab = 0; slab < 8; slab++) {
        if (tid < 128) {
            uint32_t regs[32];
            TCGEN05_LD_X32(regs, tmem + slab * 32);
            TCGEN05_WAIT_LD();
#pragma unroll
            for (int cc = 0; cc < 32; cc++) stage[tid * 33 + cc] = __uint_as_float(regs[cc]);
        }
        __syncthreads();
        for (int e = tid; e < 4096; e += GEMM_THREADS) {
            int row = e >> 5, col = e & 31;
            float vv = stage[row * 33 + col] * alpha;
            if (bias) vv += bias[bn + slab * 32 + col];
            C[(size_t)(bm + row) * N + bn + slab * 32 + col] = vv;
        }
        __syncthreads();
    }
    if (tid < 32) TCGEN05_DEALLOC(tmem, 256);

#else
    // Correct-but-slow scalar fallback for the generic compile pass.
    for (int idx = tid; idx < 128 * 256; idx += GEMM_THREADS) {
        int row = idx >> 8, col = idx & 255;
        float accv = 0.f;
        for (int kk = 0; kk < K; kk++) {
            float a = __bfloat162float(Ah[(size_t)(bm + row) * K + kk]) +
                      __bfloat162float(Al[(size_t)(bm + row) * K + kk]);
            float b = __bfloat162float(Bh[(size_t)(bn + col) * K + kk]) +
                      __bfloat162float(Bl[(size_t)(bn + col) * K + kk]);
            accv = fmaf(a, b, accv);
        }
        accv *= alpha;
        if (bias) accv += bias[bn + col];
        C[(size_t)(bm + row) * N + bn + col] = accv;
    }
    (void)sgen; (void)NC;
#endif
}

// ---------------------------------------------------------------------------
// fp32 -> (hi, lo) bf16 split helpers
// ---------------------------------------------------------------------------
__device__ __forceinline__ void split4(const float4 v,
                                       __nv_bfloat16* hi, __nv_bfloat16* lo, int i)
{
    __nv_bfloat16 h0 = __float2bfloat16(v.x), h1 = __float2bfloat16(v.y);
    __nv_bfloat16 h2 = __float2bfloat16(v.z), h3 = __float2bfloat16(v.w);
    __nv_bfloat16 l0 = __float2bfloat16(v.x - __bfloat162float(h0));
    __nv_bfloat16 l1 = __float2bfloat16(v.y - __bfloat162float(h1));
    __nv_bfloat16 l2 = __float2bfloat16(v.z - __bfloat162float(h2));
    __nv_bfloat16 l3 = __float2bfloat16(v.w - __bfloat162float(h3));
    ushort4 ph = { __bfloat16_as_ushort(h0), __bfloat16_as_ushort(h1),
                   __bfloat16_as_ushort(h2), __bfloat16_as_ushort(h3) };
    ushort4 pl = { __bfloat16_as_ushort(l0), __bfloat16_as_ushort(l1),
                   __bfloat16_as_ushort(l2), __bfloat16_as_ushort(l3) };
    ((ushort4*)hi)[i] = ph;
    ((ushort4*)lo)[i] = pl;
}

// x split, 4 float4 per thread (MLP=4).
__global__ __launch_bounds__(256)
void split32(const float* __restrict__ s, __nv_bfloat16* __restrict__ hi,
             __nv_bfloat16* __restrict__ lo)
{
    int base = blockIdx.x * 1024 + threadIdx.x;
    float4 v0 = ((const float4*)s)[base];
    float4 v1 = ((const float4*)s)[base + 256];
    float4 v2 = ((const float4*)s)[base + 512];
    float4 v3 = ((const float4*)s)[base + 768];
    split4(v0, hi, lo, base);
    split4(v1, hi, lo, base + 256);
    split4(v2, hi, lo, base + 512);
    split4(v3, hi, lo, base + 768);
}

// Weight splits into the fused [Wq;Wk*s;(Weff);Wv;Wg] + separate Wo layouts.
// 4 float4/thread. 4096 blocks:
//  [0,512)     Wq -> wall rows 0..1023
//  [512,1024)  Wk * SCALE_K -> wall rows 1024..2047
//  [1024,2048) Wv -> wall rows 3072..5119
//  [2048,3072) Wg -> wall rows 5120..7167
//  [3072,4096) Wo -> wo
__global__ __launch_bounds__(256)
void split_w(const float* __restrict__ Wq, const float* __restrict__ Wk,
             const float* __restrict__ Wv, const float* __restrict__ Wg,
             const float* __restrict__ Wo,
             __nv_bfloat16* __restrict__ wallh, __nv_bfloat16* __restrict__ walll,
             __nv_bfloat16* __restrict__ woh,  __nv_bfloat16* __restrict__ wol)
{
    int b = blockIdx.x;
    const float* src; __nv_bfloat16 *hi, *lo; int dsto; float scale = 1.f;
    if      (b < 512)  { src = Wq; hi = wallh; lo = walll; dsto = 0; }
    else if (b < 1024) { src = Wk; hi = wallh; lo = walll; dsto = 1024 * 512; b -= 512; scale = SCALE_K; }
    else if (b < 2048) { src = Wv; hi = wallh; lo = walll; dsto = 3072 * 512; b -= 1024; }
    else if (b < 3072) { src = Wg; hi = wallh; lo = walll; dsto = 5120 * 512; b -= 2048; }
    else               { src = Wo; hi = woh;   lo = wol;   dsto = 0; b -= 3072; }
    int base = b * 1024 + threadIdx.x;
#pragma unroll
    for (int u = 0; u < 4; u++) {
        int i = base + u * 256;
        float4 v = ((const float4*)src)[i];
        v.x *= scale; v.y *= scale; v.z *= scale; v.w *= scale;
        split4(v, hi, lo, dsto + i);
    }
}

// W_eff = Wkg2 @ Wkg1 -> wall rows 2048..3071, hi/lo split.
__global__ __launch_bounds__(256)
void weff_split(const float* __restrict__ W1, const float* __restrict__ W2,
                __nv_bfloat16* __restrict__ wallh, __nv_bfloat16* __restrict__ walll)
{
    __shared__ __align__(16) float s1[16][128];
    const int tid = threadIdx.x;
    const int d0  = blockIdx.x * 128;
    const int n0  = blockIdx.y * 256;

#pragma unroll
    for (int it = 0; it < 2; it++) {
        int i = it * 256 + tid;
        int r = i >> 5, c4 = i & 31;
        *(float4*)&s1[r][c4 * 4] = *(const float4*)(W1 + r * DMODEL + d0 + c4 * 4);
    }
    __syncthreads();

    const int d4 = tid & 31;
    const int nb = tid >> 5;
    for (int n = n0 + nb; n < n0 + 256; n += 8) {
        const float4 w2a = *(const float4*)(W2 + n * 16);
        const float4 w2b = *(const float4*)(W2 + n * 16 + 4);
        const float4 w2c = *(const float4*)(W2 + n * 16 + 8);
        const float4 w2d = *(const float4*)(W2 + n * 16 + 12);
        float w2[16] = { w2a.x, w2a.y, w2a.z, w2a.w, w2b.x, w2b.y, w2b.z, w2b.w,
                         w2c.x, w2c.y, w2c.z, w2c.w, w2d.x, w2d.y, w2d.z, w2d.w };
        float4 acc = {0.f, 0.f, 0.f, 0.f};
#pragma unroll
        for (int r = 0; r < 16; r++) {
            float4 v = *(const float4*)&s1[r][d4 * 4];
            acc.x = fmaf(w2[r], v.x, acc.x);
            acc.y = fmaf(w2[r], v.y, acc.y);
            acc.z = fmaf(w2[r], v.z, acc.z);
            acc.w = fmaf(w2[r], v.w, acc.w);
        }
        split4(acc, wallh, walll, (2048 + n) * 512 + (d0 >> 2) + d4);
    }
}

// fused bias: ball = [0 | 0 | bkg2 | 0 | bg]
__global__ void fill_bias(const float* __restrict__ bkg2, const float* __restrict__ bg,
                          float* __restrict__ ball)
{
    int i = blockIdx.x * 256 + threadIdx.x;
    if (i >= PS) return;
    float v = 0.f;
    if (i >= 2048 && i < 3072) v = bkg2[i - 2048];
    else if (i >= 5120)        v = bg[i - 5120];
    ball[i] = v;
}

// ===========================================================================
// CHUNKED GLA SCAN (exact algebra; fp32).  Chunk length CH=64.
// ===========================================================================

// ---------- Phase A ----------------------------------------------------------
#define PHA_SMEM (16384 * 4)
__global__ __launch_bounds__(256)
void gla_pha(const float* __restrict__ k, const float* __restrict__ kg,
             const float* __restrict__ v, float* __restrict__ a_g,
             float* __restrict__ U_g)
{
    extern __shared__ float sa[];
    float* lam = sa;                 // [64][64]
    float* kh  = sa + 4096;          // [64][64]
    float* vsm = sa + 8192;          // [64][128]

    const int blk = blockIdx.x;
    const int c   = blk & (NCK - 1);
    const int bh  = blk >> 5;
    const int b   = bh >> 4, h = bh & 15;
    const int t0  = c * CH;
    const int tid = threadIdx.x;

    const float* kb = k  + (size_t)b * SEQ * PS + h * DK;
    const float* gb = kg + (size_t)b * SEQ * PS + h * DK;
    const float* vb = v  + (size_t)b * SEQ * PS + h * DV;
    float* ag = a_g + ((size_t)bh * SEQ + t0) * DK;
    float* Ug = U_g + (size_t)blk * (DK * DV);

    for (int e = tid; e < CH * DK; e += 256) {
        int t = e >> 6, i = e & 63;
        float x = gb[(size_t)(t0 + t) * PS + i];
        float ls = fminf(x, 0.f) - log1pf(__expf(-fabsf(x)));
        lam[t * DK + i] = __expf(ls * INV_NORM);
    }
    for (int e = tid; e < CH * (DV / 4); e += 256) {
        int t = e >> 5, j4 = e & 31;
        *(float4*)&vsm[t * DV + j4 * 4] =
            *(const float4*)&vb[(size_t)(t0 + t) * PS + j4 * 4];
    }
    __syncthreads();

    if (tid < DK) {
        const int i = tid;
        float acc = 1.f;
        for (int t = 0; t < CH; t++) {
            acc *= lam[t * DK + i];
            ag[(size_t)t * DK + i] = acc;
        }
        float w = 1.f;
        for (int t = CH - 1; t >= 0; t--) {
            kh[t * DK + i] = kb[(size_t)(t0 + t) * PS + i] * w;
            w *= lam[t * DK + i];
        }
    }
    __syncthreads();

    {
        const int i0 = (tid >> 5) * 8;
        const int j0 = (tid & 31) * 4;
        float acc[8][4];
#pragma unroll
        for (int ii = 0; ii < 8; ii++)
#pragma unroll
            for (int jj = 0; jj < 4; jj++) acc[ii][jj] = 0.f;

        for (int s = 0; s < CH; s++) {
            float4 va = *(const float4*)&vsm[s * DV + j0];
            float kv[8];
            *(float4*)&kv[0] = *(const float4*)&kh[s * DK + i0];
            *(float4*)&kv[4] = *(const float4*)&kh[s * DK + i0 + 4];
#pragma unroll
            for (int ii = 0; ii < 8; ii++) {
                acc[ii][0] = fmaf(kv[ii], va.x, acc[ii][0]);
                acc[ii][1] = fmaf(kv[ii], va.y, acc[ii][1]);
                acc[ii][2] = fmaf(kv[ii], va.z, acc[ii][2]);
                acc[ii][3] = fmaf(kv[ii], va.w, acc[ii][3]);
            }
        }
#pragma unroll
        for (int ii = 0; ii < 8; ii++) {
            float4 w4 = { acc[ii][0], acc[ii][1], acc[ii][2], acc[ii][3] };
            *(float4*)&Ug[(size_t)(i0 + ii) * DV + j0] = w4;
        }
    }
}

// ---------- Phase B ----------------------------------------------------------
__global__ __launch_bounds__(256)
void gla_phb(const float* __restrict__ a_g, const float* __restrict__ U_g,
             float* __restrict__ Sp_g)
{
    const int bh  = blockIdx.x;
    const int tid = threadIdx.x;
    float S[32];
#pragma unroll
    for (int w = 0; w < 32; w++) S[w] = 0.f;

    for (int c = 0; c < NCK; c++) {
        const float* Ug = U_g + ((size_t)bh * NCK + c) * (DK * DV);
        float* Sg = Sp_g + ((size_t)bh * NCK + c) * (DK * DV);
        const float* a64 = a_g + ((size_t)bh * SEQ + c * CH + CH - 1) * DK;
#pragma unroll
        for (int w = 0; w < 8; w++) {
            int f4 = tid + w * 256;
            int i = f4 >> 5;
            float ai = a64[i];
            float4 u = ((const float4*)Ug)[f4];
            float4 s = *(float4*)&S[w * 4];
            ((float4*)Sg)[f4] = s;
            s.x = fmaf(s.x, ai, u.x);
            s.y = fmaf(s.y, ai, u.y);
            s.z = fmaf(s.z, ai, u.z);
            s.w = fmaf(s.w, ai, u.w);
            *(float4*)&S[w * 4] = s;
        }
    }
}

// ---------- Phase C (register-tiled) -----------------------------------------
#define PHC_SMEM (29248 * 4)
__global__ __launch_bounds__(256)
void gla_phc(const float* __restrict__ q, const float* __restrict__ a_g,
             const float* __restrict__ k, const float* __restrict__ Sp_g,
             const float* __restrict__ v, float* __restrict__ o)
{
    extern __shared__ float sc[];
    float* qt  = sc;            // [64][68]
    float* kT  = sc + 4352;     // [64(i)][68(s)]
    float* Am  = sc + 8704;     // [64][65]
    float* vsm = sc + 12864;    // [64][128]
    float* Ssm = sc + 21056;    // [64][128]

    const int blk = blockIdx.x;
    const int c   = blk & (NCK - 1);
    const int bh  = blk >> 5;
    const int b   = bh >> 4, h = bh & 15;
    const int t0  = c * CH;
    const int tid = threadIdx.x;

    const float* qb = q + (size_t)b * SEQ * PS + h * DK;
    const float* kb = k + (size_t)b * SEQ * PS + h * DK;
    const float* vb = v + (size_t)b * SEQ * PS + h * DV;
    const float* ag = a_g + ((size_t)bh * SEQ + t0) * DK;
    const float* Sg = Sp_g + (size_t)blk * (DK * DV);
    float* ob = o + (size_t)b * SEQ * DMODEL + h * DV;

    for (int e = tid; e < CH * DK; e += 256) {
        int t = e >> 6, i = e & 63;
        float aa = ag[(size_t)t * DK + i];
        qt[t * 68 + i] = qb[(size_t)(t0 + t) * PS + i] * aa;
        kT[i * 68 + t] = kb[(size_t)(t0 + t) * PS + i] / aa;
    }
    for (int e = tid; e < CH * (DV / 4); e += 256) {
        int t = e >> 5, j4 = e & 31;
        *(float4*)&vsm[t * DV + j4 * 4] =
            *(const float4*)&vb[(size_t)(t0 + t) * PS + j4 * 4];
        *(float4*)&Ssm[t * DV + j4 * 4] = ((const float4*)Sg)[e];
    }
    __syncthreads();

    // A = tril(qt @ kT): thread owns 2 t x 8 s
    {
        const int ta = (tid >> 3) * 2;
        const int s0 = (tid & 7) * 8;
        float acc0[8], acc1[8];
#pragma unroll
        for (int ss = 0; ss < 8; ss++) { acc0[ss] = 0.f; acc1[ss] = 0.f; }
        for (int i = 0; i < DK; i++) {
            float q0 = qt[ta * 68 + i];
            float q1 = qt[(ta + 1) * 68 + i];
            const float* kr = &kT[i * 68 + s0];
            float4 k0 = *(const float4*)&kr[0];
            float4 k1 = *(const float4*)&kr[4];
            float kv[8] = { k0.x, k0.y, k0.z, k0.w, k1.x, k1.y, k1.z, k1.w };
#pragma unroll
            for (int ss = 0; ss < 8; ss++) {
                acc0[ss] = fmaf(q0, kv[ss], acc0[ss]);
                acc1[ss] = fmaf(q1, kv[ss], acc1[ss]);
            }
        }
#pragma unroll
        for (int ss = 0; ss < 8; ss++) {
            int s = s0 + ss;
            Am[ta * 65 + s]       = (s <= ta)     ? acc0[ss] : 0.f;
            Am[(ta + 1) * 65 + s] = (s <= ta + 1) ? acc1[ss] : 0.f;
        }
    }
    __syncthreads();

    // o = A@V + qt@S_pre : thread owns 4 t x 8 j
    {
        const int to = (tid >> 4) * 4;
        const int j0 = (tid & 15) * 8;
        float acc[4][8];
#pragma unroll
        for (int r = 0; r < 4; r++)
#pragma unroll
            for (int jj = 0; jj < 8; jj++) acc[r][jj] = 0.f;

        const int smax = to + 4;
        for (int s = 0; s < smax; s++) {
            float a0 = Am[to * 65 + s];
            float a1 = Am[(to + 1) * 65 + s];
            float a2 = Am[(to + 2) * 65 + s];
            float a3 = Am[(to + 3) * 65 + s];
            const float* vr = &vsm[s * DV + j0];
            float4 v0 = *(const float4*)&vr[0];
            float4 v1 = *(const float4*)&vr[4];
            float vv[8] = { v0.x, v0.y, v0.z, v0.w, v1.x, v1.y, v1.z, v1.w };
#pragma unroll
            for (int jj = 0; jj < 8; jj++) {
                acc[0][jj] = fmaf(a0, vv[jj], acc[0][jj]);
                acc[1][jj] = fmaf(a1, vv[jj], acc[1][jj]);
                acc[2][jj] = fmaf(a2, vv[jj], acc[2][jj]);
                acc[3][jj] = fmaf(a3, vv[jj], acc[3][jj]);
            }
        }
        for (int i = 0; i < DK; i++) {
            float q0 = qt[to * 68 + i];
            float q1 = qt[(to + 1) * 68 + i];
            float q2 = qt[(to + 2) * 68 + i];
            float q3 = qt[(to + 3) * 68 + i];
            const float* sr = &Ssm[i * DV + j0];
            float4 s0v = *(const float4*)&sr[0];
            float4 s1v = *(const float4*)&sr[4];
            float sv[8] = { s0v.x, s0v.y, s0v.z, s0v.w, s1v.x, s1v.y, s1v.z, s1v.w };
#pragma unroll
            for (int jj = 0; jj < 8; jj++) {
                acc[0][jj] = fmaf(q0, sv[jj], acc[0][jj]);
                acc[1][jj] = fmaf(q1, sv[jj], acc[1][jj]);
                acc[2][jj] = fmaf(q2, sv[jj], acc[2][jj]);
                acc[3][jj] = fmaf(q3, sv[jj], acc[3][jj]);
            }
        }
#pragma unroll
        for (int r = 0; r < 4; r++) {
            float* orow = ob + (size_t)(t0 + to + r) * DMODEL + j0;
            float4 w0 = { acc[r][0], acc[r][1], acc[r][2], acc[r][3] };
            float4 w1 = { acc[r][4], acc[r][5], acc[r][6], acc[r][7] };
            *(float4*)&orow[0] = w0;
            *(float4*)&orow[4] = w1;
        }
    }
}

// ---------------------------------------------------------------------------
// LayerNorm(dv=128, no affine) + SiLU(gp) gate, fused hi/lo bf16 split.
// gp = proj + 5120, row stride PS.
// ---------------------------------------------------------------------------
__global__ __launch_bounds__(256)
void ln_gate(const float* __restrict__ o, const float* __restrict__ gp,
             __nv_bfloat16* __restrict__ zh, __nv_bfloat16* __restrict__ zl)
{
    int gw   = (blockIdx.x * blockDim.x + threadIdx.x) >> 5;   // 65536 rows
    int lane = threadIdx.x & 31;
    int m = gw >> 4, h = gw & 15;

    float4 ov = ((const float4*)(o + (size_t)gw * 128))[lane];
    float s = ov.x + ov.y + ov.z + ov.w;
#pragma unroll
    for (int d = 16; d > 0; d >>= 1) s += __shfl_xor_sync(0xffffffffu, s, d);
    float mu = s * (1.f / 128.f);

    float dx0 = ov.x - mu, dx1 = ov.y - mu, dx2 = ov.z - mu, dx3 = ov.w - mu;
    float vsum = dx0 * dx0 + dx1 * dx1 + dx2 * dx2 + dx3 * dx3;
#pragma unroll
    for (int d = 16; d > 0; d >>= 1) vsum += __shfl_xor_sync(0xffffffffu, vsum, d);
    float inv = rsqrtf(vsum * (1.f / 128.f) + 1e-5f);

    float4 gv = ((const float4*)(gp + (size_t)m * PS + (h << 7)))[lane];
    float4 z;
    z.x = (gv.x / (1.f + __expf(-gv.x))) * (dx0 * inv);
    z.y = (gv.y / (1.f + __expf(-gv.y))) * (dx1 * inv);
    z.z = (gv.z / (1.f + __expf(-gv.z))) * (dx2 * inv);
    z.w = (gv.w / (1.f + __expf(-gv.w))) * (dx3 * inv);
    split4(z, zh, zl, gw * 32 + lane);
}

// ---------------------------------------------------------------------------
extern "C" void kernel_launch(void* const* d_in, const int* in_sizes, int n_in,
                              void* d_out, int out_size)
{
    const float* x    = (const float*)d_in[0];
    const float* Wq   = (const float*)d_in[1];
    const float* Wk   = (const float*)d_in[2];
    const float* Wkg1 = (const float*)d_in[3];
    const float* Wkg2 = (const float*)d_in[4];
    const float* bkg2 = (const float*)d_in[5];
    const float* Wv   = (const float*)d_in[6];
    const float* Wg   = (const float*)d_in[7];
    const float* bg   = (const float*)d_in[8];
    const float* Wo   = (const float*)d_in[9];
    float* out = (float*)d_out;

    float *proj, *o, *ad, *Ud, *Sp, *ball;
    cudaGetSymbolAddress((void**)&proj, g_proj);
    cudaGetSymbolAddress((void**)&o,    g_o);
    cudaGetSymbolAddress((void**)&ad,   g_a);
    cudaGetSymbolAddress((void**)&Ud,   g_U);
    cudaGetSymbolAddress((void**)&Sp,   g_Sp);
    cudaGetSymbolAddress((void**)&ball, g_ball);

    __nv_bfloat16 *xh, *xl, *zh, *zl;
    __nv_bfloat16 *wallh, *walll, *woh, *wol;
    cudaGetSymbolAddress((void**)&xh,    g_xh);    cudaGetSymbolAddress((void**)&xl,    g_xl);
    cudaGetSymbolAddress((void**)&zh,    g_zh);    cudaGetSymbolAddress((void**)&zl,    g_zl);
    cudaGetSymbolAddress((void**)&wallh, g_wallh); cudaGetSymbolAddress((void**)&walll, g_walll);
    cudaGetSymbolAddress((void**)&woh,   g_woh);   cudaGetSymbolAddress((void**)&wol,   g_wol);

    cudaFuncSetAttribute(gemm3, cudaFuncAttributeMaxDynamicSharedMemorySize, GEMM_DSM);
    cudaFuncSetAttribute(gla_pha, cudaFuncAttributeMaxDynamicSharedMemorySize, PHA_SMEM);
    cudaFuncSetAttribute(gla_phc, cudaFuncAttributeMaxDynamicSharedMemorySize, PHC_SMEM);

    // splits + fused low-rank weight + fused bias
    split32<<<(MTOK * DMODEL) / 4096, 256>>>(x, xh, xl);
    split_w<<<4096, 256>>>(Wq, Wk, Wv, Wg, Wo, wallh, walll, woh, wol);
    weff_split<<<dim3(16, 4), 256>>>(Wkg1, Wkg2, wallh, walll);
    fill_bias<<<28, 256>>>(bkg2, bg, ball);

    dim3 blk(GEMM_THREADS);
    dim3 gPROJ(PS / 256, MTOK / 128);      // 28 x 32 = 896 CTAs (one launch)
    dim3 gOUT (DMODEL / 256, MTOK / 128);  // 8 x 32

    gemm3<<<gPROJ, blk, GEMM_DSM>>>(xh, xl, wallh, walll, ball, proj, PS, DMODEL, 1.f);

    // chunked scan (q=proj+0, k=+1024, kg=+2048, v=+3072; gp=+5120)
    gla_pha<<<BH * NCK, 256, PHA_SMEM>>>(proj + 1024, proj + 2048, proj + 3072, ad, Ud);
    gla_phb<<<BH, 256>>>(ad, Ud, Sp);
    gla_phc<<<BH * NCK, 256, PHC_SMEM>>>(proj, ad, proj + 1024, Sp, proj + 3072, o);

    ln_gate<<<(MTOK * NHEAD * 32) / 256, 256>>>(o, proj + 5120, zh, zl);

    gemm3<<<gOUT, blk, GEMM_DSM>>>(zh, zl, woh, wol, nullptr, out, DMODEL, DMODEL, 1.f);
}

// round 16
// speedup vs baseline: 1.1898x; 1.0543x over previous
#include <cuda_runtime.h>
#include <cuda_bf16.h>
#include <math.h>
#include <cstdint>

// ---------------------------------------------------------------------------
// Problem constants: B=2, L=2048, D=2048, H=16, dk=64, dv=128.  M = B*L = 4096.
// ---------------------------------------------------------------------------
#define MTOK 4096
#define DMODEL 2048
#define DQK 1024
#define NHEAD 16
#define DK 64
#define DV 128
#define SEQ 2048
#define SCALE_K 0.08838834764831845f   // 128^-0.5
#define INV_NORM 0.0625f               // 1/16
#define CH 64                          // scan chunk length
#define NCK (SEQ / CH)                 // 32 chunks per (b,h)
#define BH (2 * NHEAD)                 // 32
#define PS 7168                        // row stride of fused [q|k|kg|v|gp]

#if defined(__CUDA_ARCH__) && (__CUDA_ARCH__ == 1030) && defined(__CUDA_ARCH_FEAT_SM103_ALL)
#define USE_TCGEN05 1
#else
#define USE_TCGEN05 0
#endif

// ---------------------------------------------------------------------------
// Scratch (device globals: no allocation allowed)
// ---------------------------------------------------------------------------
__device__ float g_proj[MTOK * PS];               // [q | k*s | kg | v | gp]
__device__ float g_a  [BH * SEQ * DK];            // prefix decay products
__device__ float g_U  [BH * NCK * DK * DV];       // per-chunk K̂ᵀV
__device__ float g_Sp [BH * NCK * DK * DV];       // state BEFORE each chunk
__device__ float g_ball[PS];                      // fused bias vector

__device__ __nv_bfloat16 g_xh[MTOK * DMODEL],  g_xl[MTOK * DMODEL];
__device__ __nv_bfloat16 g_zh[MTOK * DMODEL],  g_zl[MTOK * DMODEL];
__device__ __nv_bfloat16 g_wallh[PS * DMODEL], g_walll[PS * DMODEL];
__device__ __nv_bfloat16 g_woh[DMODEL * DMODEL], g_wol[DMODEL * DMODEL];

// ---------------------------------------------------------------------------
// PTX helpers
// ---------------------------------------------------------------------------
__device__ __forceinline__ uint32_t smem_u32(const void* p) {
    uint32_t a;
    asm("{ .reg .u64 t; cvta.to.shared.u64 t, %1; cvt.u32.u64 %0, t; }" : "=r"(a) : "l"(p));
    return a;
}

#define SWZ(o) ((o) ^ (((o) >> 3) & 0x70))

#define CP_ASYNC16(dst, src) \
    asm volatile("cp.async.cg.shared.global [%0], [%1], 16;" :: "r"(dst), "l"(src))
#define CP_ASYNC_MBAR_ARRIVE(mb) \
    asm volatile("cp.async.mbarrier.arrive.noinc.shared.b64 [%0];" :: "r"((uint32_t)(mb)) : "memory")

#define MBARRIER_INIT(mb, cnt) \
    asm volatile("mbarrier.init.shared.b64 [%0], %1;" :: "r"((uint32_t)(mb)), "r"((uint32_t)(cnt)) : "memory")

#define MBARRIER_WAIT_PARITY(mb, par) do { \
    uint32_t _mb = (uint32_t)(mb); uint32_t _p = (uint32_t)(par); uint32_t _done; \
    asm volatile("{\n\t.reg .pred p;\n\t" \
        "mbarrier.try_wait.parity.acquire.cta.shared::cta.b64 p, [%1], %2;\n\t" \
        "selp.b32 %0, 1, 0, p;\n\t}" : "=r"(_done) : "r"(_mb), "r"(_p) : "memory"); \
    if (!_done) { \
        asm volatile("{\n\t.reg .pred P1;\n\t" \
            "WL_%=:\n\t" \
            "mbarrier.try_wait.parity.acquire.cta.shared::cta.b64 P1, [%0], %1, 0x989680;\n\t" \
            "@P1 bra.uni WD_%=;\n\t" \
            "bra.uni WL_%=;\n\t" \
            "WD_%=:\n\t}" :: "r"(_mb), "r"(_p) : "memory"); \
    } \
} while (0)

#if USE_TCGEN05
__device__ __forceinline__ uint32_t elect_one_pred() {
    uint32_t pred;
    asm volatile("{\n\t.reg .pred p;\n\telect.sync _|p, 0xFFFFFFFF;\n\t"
                 "selp.b32 %0, 1, 0, p;\n\t}" : "=r"(pred));
    return pred;
}

#define TCGEN05_ALLOC(smem_res, ncols) \
    asm volatile("tcgen05.alloc.cta_group::1.sync.aligned.shared::cta.b32 [%0], %1;" \
                 :: "r"((uint32_t)(smem_res)), "r"((uint32_t)(ncols)) : "memory")
#define TCGEN05_DEALLOC(tm, ncols) \
    asm volatile("tcgen05.dealloc.cta_group::1.sync.aligned.b32 %0, %1;" :: "r"(tm), "r"((uint32_t)(ncols)))
#define TCGEN05_RELINQ() \
    asm volatile("tcgen05.relinquish_alloc_permit.cta_group::1.sync.aligned;")
#define TCGEN05_COMMIT(mb) \
    asm volatile("tcgen05.commit.cta_group::1.mbarrier::arrive::one.shared::cluster.b64 [%0];" \
                 :: "r"((uint32_t)(mb)) : "memory")
#define TCGEN05_FENCE_AFTER() \
    asm volatile("tcgen05.fence::after_thread_sync;" ::: "memory")
#define TCGEN05_WAIT_LD() \
    asm volatile("tcgen05.wait::ld.sync.aligned;" ::: "memory")
#define FENCE_PROXY_ASYNC() \
    asm volatile("fence.proxy.async.shared::cta;" ::: "memory")

#define TCGEN05_LD_X32(r, tm) \
    asm volatile("tcgen05.ld.sync.aligned.32x32b.x32.b32 " \
        "{%0, %1, %2, %3, %4, %5, %6, %7, %8, %9, %10, %11, %12, %13, %14, %15, " \
        " %16, %17, %18, %19, %20, %21, %22, %23, %24, %25, %26, %27, %28, %29, %30, %31}, [%32];" \
        : "=r"((r)[0]),  "=r"((r)[1]),  "=r"((r)[2]),  "=r"((r)[3]), \
          "=r"((r)[4]),  "=r"((r)[5]),  "=r"((r)[6]),  "=r"((r)[7]), \
          "=r"((r)[8]),  "=r"((r)[9]),  "=r"((r)[10]), "=r"((r)[11]), \
          "=r"((r)[12]), "=r"((r)[13]), "=r"((r)[14]), "=r"((r)[15]), \
          "=r"((r)[16]), "=r"((r)[17]), "=r"((r)[18]), "=r"((r)[19]), \
          "=r"((r)[20]), "=r"((r)[21]), "=r"((r)[22]), "=r"((r)[23]), \
          "=r"((r)[24]), "=r"((r)[25]), "=r"((r)[26]), "=r"((r)[27]), \
          "=r"((r)[28]), "=r"((r)[29]), "=r"((r)[30]), "=r"((r)[31]) \
        : "r"(tm))

static constexpr uint64_t DESC_BASE_SW128 =
    (uint64_t(2) << 61) | (uint64_t(1) << 46) | (uint64_t(64) << 32) | (uint64_t(1) << 16);
#define MAKE_DESC(addr) (DESC_BASE_SW128 | ((uint64_t)((addr) >> 4) & 0x3FFF))

__device__ __forceinline__ void mma_f16_ss(uint32_t d, uint64_t ad, uint64_t bd,
                                           uint32_t idesc, uint32_t en) {
    asm volatile("{\n\t.reg .pred p;\n\tsetp.ne.u32 p, %5, 0;\n\t"
        "tcgen05.mma.cta_group::1.kind::f16 [%0], %1, %2, %3, {%4, %4, %4, %4}, p;\n\t}"
        :: "r"(d), "l"(ad), "l"(bd), "r"(idesc), "r"(0u), "r"(en) : "memory");
}
#else
__device__ __forceinline__ void mma16816(float* d, const uint32_t* a, const uint32_t* b) {
    asm volatile("mma.sync.aligned.m16n8k16.row.col.f32.bf16.bf16.f32 "
        "{%0,%1,%2,%3}, {%4,%5,%6,%7}, {%8,%9}, {%0,%1,%2,%3};"
        : "+f"(d[0]), "+f"(d[1]), "+f"(d[2]), "+f"(d[3])
        : "r"(a[0]), "r"(a[1]), "r"(a[2]), "r"(a[3]), "r"(b[0]), "r"(b[1]));
}
#endif

// ---------------------------------------------------------------------------
// bf16x3 GEMM:  C[M,N] = (A @ B^T) * alpha (+ bias), split hi/lo operands.
// Tile 128x256, K-chunk 64 (SW128), warp-specialized loaders + 1 MMA warp.
// ---------------------------------------------------------------------------
#define BUFB 98304
#define GEMM_DSM (2 * BUFB + 1024)
#define GEMM_THREADS 288

__global__ __launch_bounds__(GEMM_THREADS) __cluster_dims__(1, 1, 1)
void gemm3(const __nv_bfloat16* __restrict__ Ah, const __nv_bfloat16* __restrict__ Al,
           const __nv_bfloat16* __restrict__ Bh, const __nv_bfloat16* __restrict__ Bl,
           const float* __restrict__ bias, float* __restrict__ C,
           int N, int K, float alpha)
{
    extern __shared__ char dsm[];

    const int tid = threadIdx.x;
    const int bm = blockIdx.y * 128;
    const int bn = blockIdx.x * 256;

    const uint32_t raw = smem_u32(dsm);
    const uint32_t sbase = (raw + 1023u) & ~1023u;
    char* sgen = dsm + (sbase - raw);

    const int NC = K / 64;

#if USE_TCGEN05
    __shared__ uint32_t s_tmem;
    __shared__ __align__(16) uint64_t s_full[2];
    __shared__ __align__(16) uint64_t s_empty[2];
    const uint32_t full0  = smem_u32(&s_full[0]),  full1  = smem_u32(&s_full[1]);
    const uint32_t empty0 = smem_u32(&s_empty[0]), empty1 = smem_u32(&s_empty[1]);

    if (tid < 32) { TCGEN05_ALLOC(smem_u32(&s_tmem), 256); TCGEN05_RELINQ(); }
    if (tid == 0) {
        MBARRIER_INIT(full0, 256);  MBARRIER_INIT(full1, 256);
        MBARRIER_INIT(empty0, 1);   MBARRIER_INIT(empty1, 1);
    }
    __syncthreads();
    const uint32_t tmem = s_tmem;

    if (tid < 256) {
        const int lr  = tid >> 3;
        const int seg = tid & 7;
        for (int c = 0; c < NC; c++) {
            if (c >= 2)
                MBARRIER_WAIT_PARITY((c & 1) ? empty1 : empty0, ((c - 2) >> 1) & 1);
            const uint32_t bb = sbase + (c & 1) * BUFB;
            const int k0 = c * 64;
#pragma unroll
            for (int t2 = 0; t2 < 2; t2++) {
                const __nv_bfloat16* basep = t2 ? Al : Ah;
                uint32_t tb = bb + t2 * 16384;
#pragma unroll
                for (int ii = 0; ii < 4; ii++) {
                    int r = lr + ii * 32;
                    const void* src = basep + (size_t)(bm + r) * K + k0 + seg * 8;
                    CP_ASYNC16(tb + SWZ((uint32_t)(r * 128 + seg * 16)), src);
                }
            }
#pragma unroll
            for (int t2 = 0; t2 < 2; t2++) {
                const __nv_bfloat16* basep = t2 ? Bl : Bh;
                uint32_t tb = bb + 32768 + t2 * 32768;
#pragma unroll
                for (int ii = 0; ii < 8; ii++) {
                    int r = lr + ii * 32;
                    const void* src = basep + (size_t)(bn + r) * K + k0 + seg * 8;
                    CP_ASYNC16(tb + SWZ((uint32_t)(r * 128 + seg * 16)), src);
                }
            }
            CP_ASYNC_MBAR_ARRIVE((c & 1) ? full1 : full0);
        }
    } else if (elect_one_pred()) {
        const uint32_t IDESC = (1u << 4) | (1u << 7) | (1u << 10) | (16u << 17) | (8u << 24);
        for (int c = 0; c < NC; c++) {
            MBARRIER_WAIT_PARITY((c & 1) ? full1 : full0, (c >> 1) & 1);
            FENCE_PROXY_ASYNC();
            const uint32_t ab = sbase + (c & 1) * BUFB;
            const uint64_t dAh  = MAKE_DESC(ab);
            const uint64_t dAl  = MAKE_DESC(ab + 16384);
            const uint64_t dBh0 = MAKE_DESC(ab + 32768);
            const uint64_t dBh1 = MAKE_DESC(ab + 32768 + 16384);
            const uint64_t dBl0 = MAKE_DESC(ab + 65536);
            const uint64_t dBl1 = MAKE_DESC(ab + 65536 + 16384);
            const uint32_t en0 = (c > 0);
#pragma unroll
            for (int ks = 0; ks < 4; ks++)
                mma_f16_ss(tmem,       dAh + ks * 2, dBh0 + ks * 2, IDESC, en0 || (ks > 0));
#pragma unroll
            for (int ks = 0; ks < 4; ks++)
                mma_f16_ss(tmem + 128, dAh + ks * 2, dBh1 + ks * 2, IDESC, en0 || (ks > 0));
#pragma unroll
            for (int ks = 0; ks < 4; ks++) {
                mma_f16_ss(tmem,       dAh + ks * 2, dBl0 + ks * 2, IDESC, 1u);
                mma_f16_ss(tmem + 128, dAh + ks * 2, dBl1 + ks * 2, IDESC, 1u);
                mma_f16_ss(tmem,       dAl + ks * 2, dBh0 + ks * 2, IDESC, 1u);
                mma_f16_ss(tmem + 128, dAl + ks * 2, dBh1 + ks * 2, IDESC, 1u);
            }
            TCGEN05_COMMIT((c & 1) ? empty1 : empty0);
        }
    }

    __syncthreads();
    MBARRIER_WAIT_PARITY(((NC - 1) & 1) ? empty1 : empty0, ((NC - 1) >> 1) & 1);
    TCGEN05_FENCE_AFTER();
    __syncthreads();

    float* stage = (float*)sgen;
    for (int slab = 0; slab < 8; slab++) {
        if (tid < 128) {
            uint32_t regs[32];
            TCGEN05_LD_X32(regs, tmem + slab * 32);
            TCGEN05_WAIT_LD();
#pragma unroll
            for (int cc = 0; cc < 32; cc++) stage[tid * 33 + cc] = __uint_as_float(regs[cc]);
        }
        __syncthreads();
        for (int e = tid; e < 4096; e += GEMM_THREADS) {
            int row = e >> 5, col = e & 31;
            float vv = stage[row * 33 + col] * alpha;
            if (bias) vv += bias[bn + slab * 32 + col];
            C[(size_t)(bm + row) * N + bn + slab * 32 + col] = vv;
        }
        __syncthreads();
    }
    if (tid < 32) TCGEN05_DEALLOC(tmem, 256);

#else
    // Correct-but-slow scalar fallback for the generic compile pass.
    for (int idx = tid; idx < 128 * 256; idx += GEMM_THREADS) {
        int row = idx >> 8, col = idx & 255;
        float accv = 0.f;
        for (int kk = 0; kk < K; kk++) {
            float a = __bfloat162float(Ah[(size_t)(bm + row) * K + kk]) +
                      __bfloat162float(Al[(size_t)(bm + row) * K + kk]);
            float b = __bfloat162float(Bh[(size_t)(bn + col) * K + kk]) +
                      __bfloat162float(Bl[(size_t)(bn + col) * K + kk]);
            accv = fmaf(a, b, accv);
        }
        accv *= alpha;
        if (bias) accv += bias[bn + col];
        C[(size_t)(bm + row) * N + bn + col] = accv;
    }
    (void)sgen; (void)NC;
#endif
}

// ---------------------------------------------------------------------------
// fp32 -> (hi, lo) bf16 split helpers
// ---------------------------------------------------------------------------
__device__ __forceinline__ void split4(const float4 v,
                                       __nv_bfloat16* hi, __nv_bfloat16* lo, int i)
{
    __nv_bfloat16 h0 = __float2bfloat16(v.x), h1 = __float2bfloat16(v.y);
    __nv_bfloat16 h2 = __float2bfloat16(v.z), h3 = __float2bfloat16(v.w);
    __nv_bfloat16 l0 = __float2bfloat16(v.x - __bfloat162float(h0));
    __nv_bfloat16 l1 = __float2bfloat16(v.y - __bfloat162float(h1));
    __nv_bfloat16 l2 = __float2bfloat16(v.z - __bfloat162float(h2));
    __nv_bfloat16 l3 = __float2bfloat16(v.w - __bfloat162float(h3));
    ushort4 ph = { __bfloat16_as_ushort(h0), __bfloat16_as_ushort(h1),
                   __bfloat16_as_ushort(h2), __bfloat16_as_ushort(h3) };
    ushort4 pl = { __bfloat16_as_ushort(l0), __bfloat16_as_ushort(l1),
                   __bfloat16_as_ushort(l2), __bfloat16_as_ushort(l3) };
    ((ushort4*)hi)[i] = ph;
    ((ushort4*)lo)[i] = pl;
}

// x split (blocks 0..2047, 4 float4/thread) + fused bias fill (blocks 2048+).
__global__ __launch_bounds__(256)
void split32(const float* __restrict__ s, __nv_bfloat16* __restrict__ hi,
             __nv_bfloat16* __restrict__ lo,
             const float* __restrict__ bkg2, const float* __restrict__ bg,
             float* __restrict__ ball)
{
    if (blockIdx.x >= 2048) {
        int i = (blockIdx.x - 2048) * 256 + threadIdx.x;
        if (i < PS) {
            float v = 0.f;
            if (i >= 2048 && i < 3072) v = bkg2[i - 2048];
            else if (i >= 5120)        v = bg[i - 5120];
            ball[i] = v;
        }
        return;
    }
    int base = blockIdx.x * 1024 + threadIdx.x;
    float4 v0 = ((const float4*)s)[base];
    float4 v1 = ((const float4*)s)[base + 256];
    float4 v2 = ((const float4*)s)[base + 512];
    float4 v3 = ((const float4*)s)[base + 768];
    split4(v0, hi, lo, base);
    split4(v1, hi, lo, base + 256);
    split4(v2, hi, lo, base + 512);
    split4(v3, hi, lo, base + 768);
}

// Weight splits into fused [Wq;Wk*s;(Weff);Wv;Wg] + separate Wo layouts.
__global__ __launch_bounds__(256)
void split_w(const float* __restrict__ Wq, const float* __restrict__ Wk,
             const float* __restrict__ Wv, const float* __restrict__ Wg,
             const float* __restrict__ Wo,
             __nv_bfloat16* __restrict__ wallh, __nv_bfloat16* __restrict__ walll,
             __nv_bfloat16* __restrict__ woh,  __nv_bfloat16* __restrict__ wol)
{
    int b = blockIdx.x;
    const float* src; __nv_bfloat16 *hi, *lo; int dsto; float scale = 1.f;
    if      (b < 512)  { src = Wq; hi = wallh; lo = walll; dsto = 0; }
    else if (b < 1024) { src = Wk; hi = wallh; lo = walll; dsto = 1024 * 512; b -= 512; scale = SCALE_K; }
    else if (b < 2048) { src = Wv; hi = wallh; lo = walll; dsto = 3072 * 512; b -= 1024; }
    else if (b < 3072) { src = Wg; hi = wallh; lo = walll; dsto = 5120 * 512; b -= 2048; }
    else               { src = Wo; hi = woh;   lo = wol;   dsto = 0; b -= 3072; }
    int base = b * 1024 + threadIdx.x;
#pragma unroll
    for (int u = 0; u < 4; u++) {
        int i = base + u * 256;
        float4 v = ((const float4*)src)[i];
        v.x *= scale; v.y *= scale; v.z *= scale; v.w *= scale;
        split4(v, hi, lo, dsto + i);
    }
}

// W_eff = Wkg2 @ Wkg1 -> wall rows 2048..3071, hi/lo split.
__global__ __launch_bounds__(256)
void weff_split(const float* __restrict__ W1, const float* __restrict__ W2,
                __nv_bfloat16* __restrict__ wallh, __nv_bfloat16* __restrict__ walll)
{
    __shared__ __align__(16) float s1[16][128];
    const int tid = threadIdx.x;
    const int d0  = blockIdx.x * 128;
    const int n0  = blockIdx.y * 256;

#pragma unroll
    for (int it = 0; it < 2; it++) {
        int i = it * 256 + tid;
        int r = i >> 5, c4 = i & 31;
        *(float4*)&s1[r][c4 * 4] = *(const float4*)(W1 + r * DMODEL + d0 + c4 * 4);
    }
    __syncthreads();

    const int d4 = tid & 31;
    const int nb = tid >> 5;
    for (int n = n0 + nb; n < n0 + 256; n += 8) {
        const float4 w2a = *(const float4*)(W2 + n * 16);
        const float4 w2b = *(const float4*)(W2 + n * 16 + 4);
        const float4 w2c = *(const float4*)(W2 + n * 16 + 8);
        const float4 w2d = *(const float4*)(W2 + n * 16 + 12);
        float w2[16] = { w2a.x, w2a.y, w2a.z, w2a.w, w2b.x, w2b.y, w2b.z, w2b.w,
                         w2c.x, w2c.y, w2c.z, w2c.w, w2d.x, w2d.y, w2d.z, w2d.w };
        float4 acc = {0.f, 0.f, 0.f, 0.f};
#pragma unroll
        for (int r = 0; r < 16; r++) {
            float4 v = *(const float4*)&s1[r][d4 * 4];
            acc.x = fmaf(w2[r], v.x, acc.x);
            acc.y = fmaf(w2[r], v.y, acc.y);
            acc.z = fmaf(w2[r], v.z, acc.z);
            acc.w = fmaf(w2[r], v.w, acc.w);
        }
        split4(acc, wallh, walll, (2048 + n) * 512 + (d0 >> 2) + d4);
    }
}

// ===========================================================================
// CHUNKED GLA SCAN (exact algebra; fp32).  Chunk length CH=64.
// ===========================================================================

// ---------- Phase A ----------------------------------------------------------
#define PHA_SMEM (16384 * 4)
__global__ __launch_bounds__(256)
void gla_pha(const float* __restrict__ k, const float* __restrict__ kg,
             const float* __restrict__ v, float* __restrict__ a_g,
             float* __restrict__ U_g)
{
    extern __shared__ float sa[];
    float* lam = sa;                 // [64][64]
    float* kh  = sa + 4096;          // [64][64]
    float* vsm = sa + 8192;          // [64][128]

    const int blk = blockIdx.x;
    const int c   = blk & (NCK - 1);
    const int bh  = blk >> 5;
    const int b   = bh >> 4, h = bh & 15;
    const int t0  = c * CH;
    const int tid = threadIdx.x;

    const float* kb = k  + (size_t)b * SEQ * PS + h * DK;
    const float* gb = kg + (size_t)b * SEQ * PS + h * DK;
    const float* vb = v  + (size_t)b * SEQ * PS + h * DV;
    float* ag = a_g + ((size_t)bh * SEQ + t0) * DK;
    float* Ug = U_g + (size_t)blk * (DK * DV);

    for (int e = tid; e < CH * DK; e += 256) {
        int t = e >> 6, i = e & 63;
        float x = gb[(size_t)(t0 + t) * PS + i];
        float ls = fminf(x, 0.f) - log1pf(__expf(-fabsf(x)));
        lam[t * DK + i] = __expf(ls * INV_NORM);
    }
    for (int e = tid; e < CH * (DV / 4); e += 256) {
        int t = e >> 5, j4 = e & 31;
        *(float4*)&vsm[t * DV + j4 * 4] =
            *(const float4*)&vb[(size_t)(t0 + t) * PS + j4 * 4];
    }
    __syncthreads();

    if (tid < DK) {
        const int i = tid;
        float acc = 1.f;
        for (int t = 0; t < CH; t++) {
            acc *= lam[t * DK + i];
            ag[(size_t)t * DK + i] = acc;
        }
        float w = 1.f;
        for (int t = CH - 1; t >= 0; t--) {
            kh[t * DK + i] = kb[(size_t)(t0 + t) * PS + i] * w;
            w *= lam[t * DK + i];
        }
    }
    __syncthreads();

    {
        const int i0 = (tid >> 5) * 8;
        const int j0 = (tid & 31) * 4;
        float acc[8][4];
#pragma unroll
        for (int ii = 0; ii < 8; ii++)
#pragma unroll
            for (int jj = 0; jj < 4; jj++) acc[ii][jj] = 0.f;

        for (int s = 0; s < CH; s++) {
            float4 va = *(const float4*)&vsm[s * DV + j0];
            float kv[8];
            *(float4*)&kv[0] = *(const float4*)&kh[s * DK + i0];
            *(float4*)&kv[4] = *(const float4*)&kh[s * DK + i0 + 4];
#pragma unroll
            for (int ii = 0; ii < 8; ii++) {
                acc[ii][0] = fmaf(kv[ii], va.x, acc[ii][0]);
                acc[ii][1] = fmaf(kv[ii], va.y, acc[ii][1]);
                acc[ii][2] = fmaf(kv[ii], va.z, acc[ii][2]);
                acc[ii][3] = fmaf(kv[ii], va.w, acc[ii][3]);
            }
        }
#pragma unroll
        for (int ii = 0; ii < 8; ii++) {
            float4 w4 = { acc[ii][0], acc[ii][1], acc[ii][2], acc[ii][3] };
            *(float4*)&Ug[(size_t)(i0 + ii) * DV + j0] = w4;
        }
    }
}

// ---------- Phase B ----------------------------------------------------------
__global__ __launch_bounds__(256)
void gla_phb(const float* __restrict__ a_g, const float* __restrict__ U_g,
             float* __restrict__ Sp_g)
{
    const int bh  = blockIdx.x;
    const int tid = threadIdx.x;
    float S[32];
#pragma unroll
    for (int w = 0; w < 32; w++) S[w] = 0.f;

    for (int c = 0; c < NCK; c++) {
        const float* Ug = U_g + ((size_t)bh * NCK + c) * (DK * DV);
        float* Sg = Sp_g + ((size_t)bh * NCK + c) * (DK * DV);
        const float* a64 = a_g + ((size_t)bh * SEQ + c * CH + CH - 1) * DK;
#pragma unroll
        for (int w = 0; w < 8; w++) {
            int f4 = tid + w * 256;
            int i = f4 >> 5;
            float ai = a64[i];
            float4 u = ((const float4*)Ug)[f4];
            float4 s = *(float4*)&S[w * 4];
            ((float4*)Sg)[f4] = s;
            s.x = fmaf(s.x, ai, u.x);
            s.y = fmaf(s.y, ai, u.y);
            s.z = fmaf(s.z, ai, u.z);
            s.w = fmaf(s.w, ai, u.w);
            *(float4*)&S[w * 4] = s;
        }
    }
}

// ---------- Phase C (register-tiled, FUSED LN+SiLU gate+bf16 split) ----------
// smem floats: qt[64][68] @0 | kT[64][68] @4352 (Am aliases kT after A-stage) |
//              vsm[64][128] @8704 | Ssm[64][128] @16896  = 25088 (98 KB)
// -> 2 CTAs/SM.  kT is dead after the A-stage (A held in registers), so Am
// reuses its storage (scalar access only; stride 68).
#define PHC_SMEM (25088 * 4)
__global__ __launch_bounds__(256)
void gla_phc(const float* __restrict__ q, const float* __restrict__ a_g,
             const float* __restrict__ k, const float* __restrict__ Sp_g,
             const float* __restrict__ v, const float* __restrict__ gp,
             __nv_bfloat16* __restrict__ zh, __nv_bfloat16* __restrict__ zl)
{
    extern __shared__ float sc[];
    float* qt  = sc;            // [64][68]
    float* kT  = sc + 4352;     // [64(i)][68(s)]; Am aliases this after A-stage
    float* Am  = sc + 4352;
    float* vsm = sc + 8704;     // [64][128]
    float* Ssm = sc + 16896;    // [64][128]

    const int blk = blockIdx.x;
    const int c   = blk & (NCK - 1);
    const int bh  = blk >> 5;
    const int b   = bh >> 4, h = bh & 15;
    const int t0  = c * CH;
    const int tid = threadIdx.x;

    const float* qb = q + (size_t)b * SEQ * PS + h * DK;
    const float* kb = k + (size_t)b * SEQ * PS + h * DK;
    const float* vb = v + (size_t)b * SEQ * PS + h * DV;
    const float* gpb = gp + (size_t)b * SEQ * PS + h * DV;
    const float* ag = a_g + ((size_t)bh * SEQ + t0) * DK;
    const float* Sg = Sp_g + (size_t)blk * (DK * DV);

    for (int e = tid; e < CH * DK; e += 256) {
        int t = e >> 6, i = e & 63;
        float aa = ag[(size_t)t * DK + i];
        qt[t * 68 + i] = qb[(size_t)(t0 + t) * PS + i] * aa;
        kT[i * 68 + t] = kb[(size_t)(t0 + t) * PS + i] / aa;
    }
    for (int e = tid; e < CH * (DV / 4); e += 256) {
        int t = e >> 5, j4 = e & 31;
        *(float4*)&vsm[t * DV + j4 * 4] =
            *(const float4*)&vb[(size_t)(t0 + t) * PS + j4 * 4];
        *(float4*)&Ssm[t * DV + j4 * 4] = ((const float4*)Sg)[e];
    }
    __syncthreads();

    // A = tril(qt @ kT): thread owns 2 t x 8 s (held in regs through the
    // barrier, then stored into Am which ALIASES kT).
    {
        const int ta = (tid >> 3) * 2;
        const int s0 = (tid & 7) * 8;
        float acc0[8], acc1[8];
#pragma unroll
        for (int ss = 0; ss < 8; ss++) { acc0[ss] = 0.f; acc1[ss] = 0.f; }
        for (int i = 0; i < DK; i++) {
            float q0 = qt[ta * 68 + i];
            float q1 = qt[(ta + 1) * 68 + i];
            const float* kr = &kT[i * 68 + s0];
            float4 k0 = *(const float4*)&kr[0];
            float4 k1 = *(const float4*)&kr[4];
            float kv[8] = { k0.x, k0.y, k0.z, k0.w, k1.x, k1.y, k1.z, k1.w };
#pragma unroll
            for (int ss = 0; ss < 8; ss++) {
                acc0[ss] = fmaf(q0, kv[ss], acc0[ss]);
                acc1[ss] = fmaf(q1, kv[ss], acc1[ss]);
            }
        }
        __syncthreads();             // all kT reads complete before overwrite
#pragma unroll
        for (int ss = 0; ss < 8; ss++) {
            int s = s0 + ss;
            Am[ta * 68 + s]       = (s <= ta)     ? acc0[ss] : 0.f;
            Am[(ta + 1) * 68 + s] = (s <= ta + 1) ? acc1[ss] : 0.f;
        }
    }
    __syncthreads();

    // o = A@V + qt@S_pre : thread owns 4 t x 8 j; then fused LN+gate+split.
    {
        const int to = (tid >> 4) * 4;
        const int j0 = (tid & 15) * 8;
        float acc[4][8];
#pragma unroll
        for (int r = 0; r < 4; r++)
#pragma unroll
            for (int jj = 0; jj < 8; jj++) acc[r][jj] = 0.f;

        const int smax = to + 4;
        for (int s = 0; s < smax; s++) {
            float a0 = Am[to * 68 + s];
            float a1 = Am[(to + 1) * 68 + s];
            float a2 = Am[(to + 2) * 68 + s];
            float a3 = Am[(to + 3) * 68 + s];
            const float* vr = &vsm[s * DV + j0];
            float4 v0 = *(const float4*)&vr[0];
            float4 v1 = *(const float4*)&vr[4];
            float vv[8] = { v0.x, v0.y, v0.z, v0.w, v1.x, v1.y, v1.z, v1.w };
#pragma unroll
            for (int jj = 0; jj < 8; jj++) {
                acc[0][jj] = fmaf(a0, vv[jj], acc[0][jj]);
                acc[1][jj] = fmaf(a1, vv[jj], acc[1][jj]);
                acc[2][jj] = fmaf(a2, vv[jj], acc[2][jj]);
                acc[3][jj] = fmaf(a3, vv[jj], acc[3][jj]);
            }
        }
        for (int i = 0; i < DK; i++) {
            float q0 = qt[to * 68 + i];
            float q1 = qt[(to + 1) * 68 + i];
            float q2 = qt[(to + 2) * 68 + i];
            float q3 = qt[(to + 3) * 68 + i];
            const float* sr = &Ssm[i * DV + j0];
            float4 s0v = *(const float4*)&sr[0];
            float4 s1v = *(const float4*)&sr[4];
            float sv[8] = { s0v.x, s0v.y, s0v.z, s0v.w, s1v.x, s1v.y, s1v.z, s1v.w };
#pragma unroll
            for (int jj = 0; jj < 8; jj++) {
                acc[0][jj] = fmaf(q0, sv[jj], acc[0][jj]);
                acc[1][jj] = fmaf(q1, sv[jj], acc[1][jj]);
                acc[2][jj] = fmaf(q2, sv[jj], acc[2][jj]);
                acc[3][jj] = fmaf(q3, sv[jj], acc[3][jj]);
            }
        }

        // LayerNorm across each row's 128 cols: 16 threads per row group
        // (lanes tid&15 -> shfl.xor 1/2/4/8 stays inside the group), then
        // SiLU(gp) gate and hi/lo bf16 split straight to zh/zl.
#pragma unroll
        for (int r = 0; r < 4; r++) {
            float s = 0.f;
#pragma unroll
            for (int jj = 0; jj < 8; jj++) s += acc[r][jj];
            s += __shfl_xor_sync(0xffffffffu, s, 8);
            s += __shfl_xor_sync(0xffffffffu, s, 4);
            s += __shfl_xor_sync(0xffffffffu, s, 2);
            s += __shfl_xor_sync(0xffffffffu, s, 1);
            float mu = s * (1.f / 128.f);

            float dx[8], vs = 0.f;
#pragma unroll
            for (int jj = 0; jj < 8; jj++) { dx[jj] = acc[r][jj] - mu; vs += dx[jj] * dx[jj]; }
            vs += __shfl_xor_sync(0xffffffffu, vs, 8);
            vs += __shfl_xor_sync(0xffffffffu, vs, 4);
            vs += __shfl_xor_sync(0xffffffffu, vs, 2);
            vs += __shfl_xor_sync(0xffffffffu, vs, 1);
            float inv = rsqrtf(vs * (1.f / 128.f) + 1e-5f);

            const int t = t0 + to + r;
            const float* gr = gpb + (size_t)t * PS + j0;
            float4 g0 = *(const float4*)&gr[0];
            float4 g1 = *(const float4*)&gr[4];
            float gv[8] = { g0.x, g0.y, g0.z, g0.w, g1.x, g1.y, g1.z, g1.w };
            float z[8];
#pragma unroll
            for (int jj = 0; jj < 8; jj++)
                z[jj] = (gv[jj] / (1.f + __expf(-gv[jj]))) * (dx[jj] * inv);

            const int m = b * SEQ + t;
            const int zi = (m * DMODEL + h * DV + j0) >> 2;
            float4 z0 = { z[0], z[1], z[2], z[3] };
            float4 z1 = { z[4], z[5], z[6], z[7] };
            split4(z0, zh, zl, zi);
            split4(z1, zh, zl, zi + 1);
        }
    }
}

// ---------------------------------------------------------------------------
extern "C" void kernel_launch(void* const* d_in, const int* in_sizes, int n_in,
                              void* d_out, int out_size)
{
    const float* x    = (const float*)d_in[0];
    const float* Wq   = (const float*)d_in[1];
    const float* Wk   = (const float*)d_in[2];
    const float* Wkg1 = (const float*)d_in[3];
    const float* Wkg2 = (const float*)d_in[4];
    const float* bkg2 = (const float*)d_in[5];
    const float* Wv   = (const float*)d_in[6];
    const float* Wg   = (const float*)d_in[7];
    const float* bg   = (const float*)d_in[8];
    const float* Wo   = (const float*)d_in[9];
    float* out = (float*)d_out;

    float *proj, *ad, *Ud, *Sp, *ball;
    cudaGetSymbolAddress((void**)&proj, g_proj);
    cudaGetSymbolAddress((void**)&ad,   g_a);
    cudaGetSymbolAddress((void**)&Ud,   g_U);
    cudaGetSymbolAddress((void**)&Sp,   g_Sp);
    cudaGetSymbolAddress((void**)&ball, g_ball);

    __nv_bfloat16 *xh, *xl, *zh, *zl;
    __nv_bfloat16 *wallh, *walll, *woh, *wol;
    cudaGetSymbolAddress((void**)&xh,    g_xh);    cudaGetSymbolAddress((void**)&xl,    g_xl);
    cudaGetSymbolAddress((void**)&zh,    g_zh);    cudaGetSymbolAddress((void**)&zl,    g_zl);
    cudaGetSymbolAddress((void**)&wallh, g_wallh); cudaGetSymbolAddress((void**)&walll, g_walll);
    cudaGetSymbolAddress((void**)&woh,   g_woh);   cudaGetSymbolAddress((void**)&wol,   g_wol);

    cudaFuncSetAttribute(gemm3, cudaFuncAttributeMaxDynamicSharedMemorySize, GEMM_DSM);
    cudaFuncSetAttribute(gla_pha, cudaFuncAttributeMaxDynamicSharedMemorySize, PHA_SMEM);
    cudaFuncSetAttribute(gla_phc, cudaFuncAttributeMaxDynamicSharedMemorySize, PHC_SMEM);

    // x split + bias fill (one launch), weight splits, low-rank weight product
    split32<<<2048 + 28, 256>>>(x, xh, xl, bkg2, bg, ball);
    split_w<<<4096, 256>>>(Wq, Wk, Wv, Wg, Wo, wallh, walll, woh, wol);
    weff_split<<<dim3(16, 4), 256>>>(Wkg1, Wkg2, wallh, walll);

    dim3 blk(GEMM_THREADS);
    dim3 gPROJ(PS / 256, MTOK / 128);      // 28 x 32 = 896 CTAs (one launch)
    dim3 gOUT (DMODEL / 256, MTOK / 128);  // 8 x 32

    gemm3<<<gPROJ, blk, GEMM_DSM>>>(xh, xl, wallh, walll, ball, proj, PS, DMODEL, 1.f);

    // chunked scan (q=proj+0, k=+1024, kg=+2048, v=+3072; gp=+5120)
    gla_pha<<<BH * NCK, 256, PHA_SMEM>>>(proj + 1024, proj + 2048, proj + 3072, ad, Ud);
    gla_phb<<<BH, 256>>>(ad, Ud, Sp);
    gla_phc<<<BH * NCK, 256, PHC_SMEM>>>(proj, ad, proj + 1024, Sp, proj + 3072,
                                         proj + 5120, zh, zl);

    gemm3<<<gOUT, blk, GEMM_DSM>>>(zh, zl, woh, wol, nullptr, out, DMODEL, DMODEL, 1.f);
}

// round 17
// speedup vs baseline: 1.2054x; 1.0132x over previous
#include <cuda_runtime.h>
#include <cuda.h>
#include <cuda_bf16.h>
#include <math.h>
#include <cstdint>

// ---------------------------------------------------------------------------
// Problem constants: B=2, L=2048, D=2048, H=16, dk=64, dv=128.  M = B*L = 4096.
// ---------------------------------------------------------------------------
#define MTOK 4096
#define DMODEL 2048
#define DQK 1024
#define NHEAD 16
#define DK 64
#define DV 128
#define SEQ 2048
#define SCALE_K 0.08838834764831845f   // 128^-0.5
#define INV_NORM 0.0625f               // 1/16
#define CH 64                          // scan chunk length
#define NCK (SEQ / CH)                 // 32 chunks per (b,h)
#define BH (2 * NHEAD)                 // 32
#define PS 7168                        // row stride of fused [q|k|kg|v|gp]

#if defined(__CUDA_ARCH__) && (__CUDA_ARCH__ == 1030) && defined(__CUDA_ARCH_FEAT_SM103_ALL)
#define USE_TCGEN05 1
#else
#define USE_TCGEN05 0
#endif

// ---------------------------------------------------------------------------
// Scratch (device globals: no allocation allowed)
// ---------------------------------------------------------------------------
__device__ float g_proj[MTOK * PS];               // [q | k*s | kg | v | gp]
__device__ float g_a  [BH * SEQ * DK];            // prefix decay products
__device__ float g_U  [BH * NCK * DK * DV];       // per-chunk K̂ᵀV
__device__ float g_Sp [BH * NCK * DK * DV];       // state BEFORE each chunk
__device__ float g_ball[PS];                      // fused bias vector

__device__ __align__(1024) __nv_bfloat16 g_xh[MTOK * DMODEL];
__device__ __align__(1024) __nv_bfloat16 g_xl[MTOK * DMODEL];
__device__ __align__(1024) __nv_bfloat16 g_zh[MTOK * DMODEL];
__device__ __align__(1024) __nv_bfloat16 g_zl[MTOK * DMODEL];
__device__ __align__(1024) __nv_bfloat16 g_wallh[PS * DMODEL];
__device__ __align__(1024) __nv_bfloat16 g_walll[PS * DMODEL];
__device__ __align__(1024) __nv_bfloat16 g_woh[DMODEL * DMODEL];
__device__ __align__(1024) __nv_bfloat16 g_wol[DMODEL * DMODEL];

// ---------------------------------------------------------------------------
// PTX helpers
// ---------------------------------------------------------------------------
__device__ __forceinline__ uint32_t smem_u32(const void* p) {
    uint32_t a;
    asm("{ .reg .u64 t; cvta.to.shared.u64 t, %1; cvt.u32.u64 %0, t; }" : "=r"(a) : "l"(p));
    return a;
}

#define MBARRIER_INIT(mb, cnt) \
    asm volatile("mbarrier.init.shared.b64 [%0], %1;" :: "r"((uint32_t)(mb)), "r"((uint32_t)(cnt)) : "memory")
#define MBARRIER_EXPECT_TX(mb, bytes) \
    asm volatile("mbarrier.arrive.expect_tx.shared.b64 _, [%0], %1;" \
                 :: "r"((uint32_t)(mb)), "r"((uint32_t)(bytes)) : "memory")

#define MBARRIER_WAIT_PARITY(mb, par) do { \
    uint32_t _mb = (uint32_t)(mb); uint32_t _p = (uint32_t)(par); uint32_t _done; \
    asm volatile("{\n\t.reg .pred p;\n\t" \
        "mbarrier.try_wait.parity.acquire.cta.shared::cta.b64 p, [%1], %2;\n\t" \
        "selp.b32 %0, 1, 0, p;\n\t}" : "=r"(_done) : "r"(_mb), "r"(_p) : "memory"); \
    if (!_done) { \
        asm volatile("{\n\t.reg .pred P1;\n\t" \
            "WL_%=:\n\t" \
            "mbarrier.try_wait.parity.acquire.cta.shared::cta.b64 P1, [%0], %1, 0x989680;\n\t" \
            "@P1 bra.uni WD_%=;\n\t" \
            "bra.uni WL_%=;\n\t" \
            "WD_%=:\n\t}" :: "r"(_mb), "r"(_p) : "memory"); \
    } \
} while (0)

#if USE_TCGEN05
__device__ __forceinline__ uint32_t elect_one_pred() {
    uint32_t pred;
    asm volatile("{\n\t.reg .pred p;\n\telect.sync _|p, 0xFFFFFFFF;\n\t"
                 "selp.b32 %0, 1, 0, p;\n\t}" : "=r"(pred));
    return pred;
}

#define TMA_LOAD_2D(dst, map, cx, cy, mb) \
    asm volatile("cp.async.bulk.tensor.2d.shared::cta.global.tile.mbarrier::complete_tx::bytes " \
                 "[%0], [%1, {%2, %3}], [%4];" \
                 :: "r"((uint32_t)(dst)), "l"(map), "r"((int32_t)(cx)), "r"((int32_t)(cy)), \
                    "r"((uint32_t)(mb)) : "memory")

#define TCGEN05_ALLOC(smem_res, ncols) \
    asm volatile("tcgen05.alloc.cta_group::1.sync.aligned.shared::cta.b32 [%0], %1;" \
                 :: "r"((uint32_t)(smem_res)), "r"((uint32_t)(ncols)) : "memory")
#define TCGEN05_DEALLOC(tm, ncols) \
    asm volatile("tcgen05.dealloc.cta_group::1.sync.aligned.b32 %0, %1;" :: "r"(tm), "r"((uint32_t)(ncols)))
#define TCGEN05_RELINQ() \
    asm volatile("tcgen05.relinquish_alloc_permit.cta_group::1.sync.aligned;")
#define TCGEN05_COMMIT(mb) \
    asm volatile("tcgen05.commit.cta_group::1.mbarrier::arrive::one.shared::cluster.b64 [%0];" \
                 :: "r"((uint32_t)(mb)) : "memory")
#define TCGEN05_FENCE_AFTER() \
    asm volatile("tcgen05.fence::after_thread_sync;" ::: "memory")
#define TCGEN05_WAIT_LD() \
    asm volatile("tcgen05.wait::ld.sync.aligned;" ::: "memory")

#define TCGEN05_LD_X32(r, tm) \
    asm volatile("tcgen05.ld.sync.aligned.32x32b.x32.b32 " \
        "{%0, %1, %2, %3, %4, %5, %6, %7, %8, %9, %10, %11, %12, %13, %14, %15, " \
        " %16, %17, %18, %19, %20, %21, %22, %23, %24, %25, %26, %27, %28, %29, %30, %31}, [%32];" \
        : "=r"((r)[0]),  "=r"((r)[1]),  "=r"((r)[2]),  "=r"((r)[3]), \
          "=r"((r)[4]),  "=r"((r)[5]),  "=r"((r)[6]),  "=r"((r)[7]), \
          "=r"((r)[8]),  "=r"((r)[9]),  "=r"((r)[10]), "=r"((r)[11]), \
          "=r"((r)[12]), "=r"((r)[13]), "=r"((r)[14]), "=r"((r)[15]), \
          "=r"((r)[16]), "=r"((r)[17]), "=r"((r)[18]), "=r"((r)[19]), \
          "=r"((r)[20]), "=r"((r)[21]), "=r"((r)[22]), "=r"((r)[23]), \
          "=r"((r)[24]), "=r"((r)[25]), "=r"((r)[26]), "=r"((r)[27]), \
          "=r"((r)[28]), "=r"((r)[29]), "=r"((r)[30]), "=r"((r)[31]) \
        : "r"(tm))

// K-major SW64 descriptor: layout=4 (SW64), version=1, SBO=32, LBO=1
// (validated on-HW in round 12 of this session)
static constexpr uint64_t DESC_BASE_SW64 =
    (uint64_t(4) << 61) | (uint64_t(1) << 46) | (uint64_t(32) << 32) | (uint64_t(1) << 16);
#define MAKE_DESC64(addr) (DESC_BASE_SW64 | ((uint64_t)((addr) >> 4) & 0x3FFF))

__device__ __forceinline__ void mma_f16_ss(uint32_t d, uint64_t ad, uint64_t bd,
                                           uint32_t idesc, uint32_t en) {
    asm volatile("{\n\t.reg .pred p;\n\tsetp.ne.u32 p, %5, 0;\n\t"
        "tcgen05.mma.cta_group::1.kind::f16 [%0], %1, %2, %3, {%4, %4, %4, %4}, p;\n\t}"
        :: "r"(d), "l"(ad), "l"(bd), "r"(idesc), "r"(0u), "r"(en) : "memory");
}
#endif

// ---------------------------------------------------------------------------
// bf16x3 GEMM, TMA edition:  C[M,N] = (A @ B^T) * alpha (+ bias).
// 256x256 output tile, K-chunk 32 (SW64, 64B rows), double-buffered.
//   tid==0: TMA producer (4 bulk-tensor loads + expect_tx per chunk)
//   warp 1: MMA consumer (24 MMAs -> commit empty)
// Four 128x128 fp32 accumulators in TMEM (512 cols).
// Stage: Ah 16K | Al 16K | Bh 16K | Bl 16K = 64KB; two stages (129KB smem).
// ---------------------------------------------------------------------------
#define BUFB 65536
#define GEMM_DSM (2 * BUFB + 1024)
#define GEMM_THREADS 256

__global__ __launch_bounds__(GEMM_THREADS) __cluster_dims__(1, 1, 1)
void gemm3(const __grid_constant__ CUtensorMap tmAh,
           const __grid_constant__ CUtensorMap tmAl,
           const __grid_constant__ CUtensorMap tmBh,
           const __grid_constant__ CUtensorMap tmBl,
           const __nv_bfloat16* __restrict__ Ah, const __nv_bfloat16* __restrict__ Al,
           const __nv_bfloat16* __restrict__ Bh, const __nv_bfloat16* __restrict__ Bl,
           const float* __restrict__ bias, float* __restrict__ C,
           int N, int K, float alpha)
{
    extern __shared__ char dsm[];

    const int tid = threadIdx.x;
    const int bm = blockIdx.y * 256;
    const int bn = blockIdx.x * 256;

    const uint32_t raw = smem_u32(dsm);
    const uint32_t sbase = (raw + 1023u) & ~1023u;
    char* sgen = dsm + (sbase - raw);

    const int NC = K / 32;

#if USE_TCGEN05
    __shared__ uint32_t s_tmem;
    __shared__ __align__(16) uint64_t s_full[2];
    __shared__ __align__(16) uint64_t s_empty[2];
    const uint32_t full0  = smem_u32(&s_full[0]),  full1  = smem_u32(&s_full[1]);
    const uint32_t empty0 = smem_u32(&s_empty[0]), empty1 = smem_u32(&s_empty[1]);

    if (tid < 32) { TCGEN05_ALLOC(smem_u32(&s_tmem), 512); TCGEN05_RELINQ(); }
    if (tid == 0) {
        MBARRIER_INIT(full0, 1);   MBARRIER_INIT(full1, 1);
        MBARRIER_INIT(empty0, 1);  MBARRIER_INIT(empty1, 1);
    }
    __syncthreads();
    const uint32_t tmem = s_tmem;

    if (tid == 0) {
        // ---------------- TMA producer ----------------
        for (int c = 0; c < NC; c++) {
            if (c >= 2)
                MBARRIER_WAIT_PARITY((c & 1) ? empty1 : empty0, ((c - 2) >> 1) & 1);
            const uint32_t bb = sbase + (c & 1) * BUFB;
            const uint32_t fb = (c & 1) ? full1 : full0;
            const int k0 = c * 32;
            MBARRIER_EXPECT_TX(fb, 65536);
            TMA_LOAD_2D(bb,         &tmAh, k0, bm, fb);
            TMA_LOAD_2D(bb + 16384, &tmAl, k0, bm, fb);
            TMA_LOAD_2D(bb + 32768, &tmBh, k0, bn, fb);
            TMA_LOAD_2D(bb + 49152, &tmBl, k0, bn, fb);
        }
    } else if (tid >= 32 && tid < 64 && elect_one_pred()) {
        // ---------------- MMA consumer ----------------
        const uint32_t IDESC = (1u << 4) | (1u << 7) | (1u << 10) | (16u << 17) | (8u << 24);
        for (int c = 0; c < NC; c++) {
            MBARRIER_WAIT_PARITY((c & 1) ? full1 : full0, (c >> 1) & 1);
            const uint32_t ab = sbase + (c & 1) * BUFB;
            const uint64_t dAh = MAKE_DESC64(ab);
            const uint64_t dAl = MAKE_DESC64(ab + 16384);
            const uint64_t dBh = MAKE_DESC64(ab + 32768);
            const uint64_t dBl = MAKE_DESC64(ab + 49152);
            const uint32_t en0 = (c > 0);
            // hi*hi (init accumulators on first k-step of chunk 0)
#pragma unroll
            for (int ks = 0; ks < 2; ks++)
#pragma unroll
                for (int mh = 0; mh < 2; mh++)
#pragma unroll
                    for (int nh = 0; nh < 2; nh++)
                        mma_f16_ss(tmem + (mh * 2 + nh) * 128,
                                   dAh + mh * 512 + ks * 2,
                                   dBh + nh * 512 + ks * 2,
                                   IDESC, en0 || (ks > 0));
            // cross products
#pragma unroll
            for (int ks = 0; ks < 2; ks++)
#pragma unroll
                for (int mh = 0; mh < 2; mh++)
#pragma unroll
                    for (int nh = 0; nh < 2; nh++) {
                        uint32_t d = tmem + (mh * 2 + nh) * 128;
                        mma_f16_ss(d, dAh + mh * 512 + ks * 2,
                                      dBl + nh * 512 + ks * 2, IDESC, 1u);
                        mma_f16_ss(d, dAl + mh * 512 + ks * 2,
                                      dBh + nh * 512 + ks * 2, IDESC, 1u);
                    }
            TCGEN05_COMMIT((c & 1) ? empty1 : empty0);
        }
    }

    __syncthreads();
    MBARRIER_WAIT_PARITY(((NC - 1) & 1) ? empty1 : empty0, ((NC - 1) >> 1) & 1);
    TCGEN05_FENCE_AFTER();
    __syncthreads();

    // epilogue: 4 accumulators x 4 slabs of 32 cols
    float* stage = (float*)sgen;
    for (int acc = 0; acc < 4; acc++) {
        const int mh = acc >> 1, nh = acc & 1;
        for (int slab = 0; slab < 4; slab++) {
            if (tid < 128) {
                uint32_t regs[32];
                TCGEN05_LD_X32(regs, tmem + acc * 128 + slab * 32);
                TCGEN05_WAIT_LD();
#pragma unroll
                for (int cc = 0; cc < 32; cc++) stage[tid * 33 + cc] = __uint_as_float(regs[cc]);
            }
            __syncthreads();
            for (int e = tid; e < 4096; e += GEMM_THREADS) {
                int row = e >> 5, col = e & 31;
                float vv = stage[row * 33 + col] * alpha;
                int gcol = bn + nh * 128 + slab * 32 + col;
                if (bias) vv += bias[gcol];
                C[(size_t)(bm + mh * 128 + row) * N + gcol] = vv;
            }
            __syncthreads();
        }
    }
    if (tid < 32) TCGEN05_DEALLOC(tmem, 512);

#else
    // Correct-but-slow scalar fallback for the generic compile pass (never
    // selected at runtime; the sm_103a image always exists).
    for (int idx = tid; idx < 256 * 256; idx += GEMM_THREADS) {
        int row = idx >> 8, col = idx & 255;
        float accv = 0.f;
        for (int kk = 0; kk < K; kk++) {
            float a = __bfloat162float(Ah[(size_t)(bm + row) * K + kk]) +
                      __bfloat162float(Al[(size_t)(bm + row) * K + kk]);
            float b = __bfloat162float(Bh[(size_t)(bn + col) * K + kk]) +
                      __bfloat162float(Bl[(size_t)(bn + col) * K + kk]);
            accv = fmaf(a, b, accv);
        }
        accv *= alpha;
        if (bias) accv += bias[bn + col];
        C[(size_t)(bm + row) * N + bn + col] = accv;
    }
    (void)sgen; (void)NC;
#endif
}

// ---------------------------------------------------------------------------
// fp32 -> (hi, lo) bf16 split helpers
// ---------------------------------------------------------------------------
__device__ __forceinline__ void split4(const float4 v,
                                       __nv_bfloat16* hi, __nv_bfloat16* lo, int i)
{
    __nv_bfloat16 h0 = __float2bfloat16(v.x), h1 = __float2bfloat16(v.y);
    __nv_bfloat16 h2 = __float2bfloat16(v.z), h3 = __float2bfloat16(v.w);
    __nv_bfloat16 l0 = __float2bfloat16(v.x - __bfloat162float(h0));
    __nv_bfloat16 l1 = __float2bfloat16(v.y - __bfloat162float(h1));
    __nv_bfloat16 l2 = __float2bfloat16(v.z - __bfloat162float(h2));
    __nv_bfloat16 l3 = __float2bfloat16(v.w - __bfloat162float(h3));
    ushort4 ph = { __bfloat16_as_ushort(h0), __bfloat16_as_ushort(h1),
                   __bfloat16_as_ushort(h2), __bfloat16_as_ushort(h3) };
    ushort4 pl = { __bfloat16_as_ushort(l0), __bfloat16_as_ushort(l1),
                   __bfloat16_as_ushort(l2), __bfloat16_as_ushort(l3) };
    ((ushort4*)hi)[i] = ph;
    ((ushort4*)lo)[i] = pl;
}

// x split (blocks 0..2047, 4 float4/thread) + fused bias fill (blocks 2048+).
__global__ __launch_bounds__(256)
void split32(const float* __restrict__ s, __nv_bfloat16* __restrict__ hi,
             __nv_bfloat16* __restrict__ lo,
             const float* __restrict__ bkg2, const float* __restrict__ bg,
             float* __restrict__ ball)
{
    if (blockIdx.x >= 2048) {
        int i = (blockIdx.x - 2048) * 256 + threadIdx.x;
        if (i < PS) {
            float v = 0.f;
            if (i >= 2048 && i < 3072) v = bkg2[i - 2048];
            else if (i >= 5120)        v = bg[i - 5120];
            ball[i] = v;
        }
        return;
    }
    int base = blockIdx.x * 1024 + threadIdx.x;
    float4 v0 = ((const float4*)s)[base];
    float4 v1 = ((const float4*)s)[base + 256];
    float4 v2 = ((const float4*)s)[base + 512];
    float4 v3 = ((const float4*)s)[base + 768];
    split4(v0, hi, lo, base);
    split4(v1, hi, lo, base + 256);
    split4(v2, hi, lo, base + 512);
    split4(v3, hi, lo, base + 768);
}

// Weight splits into fused [Wq;Wk*s;(Weff);Wv;Wg] + separate Wo layouts.
__global__ __launch_bounds__(256)
void split_w(const float* __restrict__ Wq, const float* __restrict__ Wk,
             const float* __restrict__ Wv, const float* __restrict__ Wg,
             const float* __restrict__ Wo,
             __nv_bfloat16* __restrict__ wallh, __nv_bfloat16* __restrict__ walll,
             __nv_bfloat16* __restrict__ woh,  __nv_bfloat16* __restrict__ wol)
{
    int b = blockIdx.x;
    const float* src; __nv_bfloat16 *hi, *lo; int dsto; float scale = 1.f;
    if      (b < 512)  { src = Wq; hi = wallh; lo = walll; dsto = 0; }
    else if (b < 1024) { src = Wk; hi = wallh; lo = walll; dsto = 1024 * 512; b -= 512; scale = SCALE_K; }
    else if (b < 2048) { src = Wv; hi = wallh; lo = walll; dsto = 3072 * 512; b -= 1024; }
    else if (b < 3072) { src = Wg; hi = wallh; lo = walll; dsto = 5120 * 512; b -= 2048; }
    else               { src = Wo; hi = woh;   lo = wol;   dsto = 0; b -= 3072; }
    int base = b * 1024 + threadIdx.x;
#pragma unroll
    for (int u = 0; u < 4; u++) {
        int i = base + u * 256;
        float4 v = ((const float4*)src)[i];
        v.x *= scale; v.y *= scale; v.z *= scale; v.w *= scale;
        split4(v, hi, lo, dsto + i);
    }
}

// W_eff = Wkg2 @ Wkg1 -> wall rows 2048..3071, hi/lo split.
__global__ __launch_bounds__(256)
void weff_split(const float* __restrict__ W1, const float* __restrict__ W2,
                __nv_bfloat16* __restrict__ wallh, __nv_bfloat16* __restrict__ walll)
{
    __shared__ __align__(16) float s1[16][128];
    const int tid = threadIdx.x;
    const int d0  = blockIdx.x * 128;
    const int n0  = blockIdx.y * 256;

#pragma unroll
    for (int it = 0; it < 2; it++) {
        int i = it * 256 + tid;
        int r = i >> 5, c4 = i & 31;
        *(float4*)&s1[r][c4 * 4] = *(const float4*)(W1 + r * DMODEL + d0 + c4 * 4);
    }
    __syncthreads();

    const int d4 = tid & 31;
    const int nb = tid >> 5;
    for (int n = n0 + nb; n < n0 + 256; n += 8) {
        const float4 w2a = *(const float4*)(W2 + n * 16);
        const float4 w2b = *(const float4*)(W2 + n * 16 + 4);
        const float4 w2c = *(const float4*)(W2 + n * 16 + 8);
        const float4 w2d = *(const float4*)(W2 + n * 16 + 12);
        float w2[16] = { w2a.x, w2a.y, w2a.z, w2a.w, w2b.x, w2b.y, w2b.z, w2b.w,
                         w2c.x, w2c.y, w2c.z, w2c.w, w2d.x, w2d.y, w2d.z, w2d.w };
        float4 acc = {0.f, 0.f, 0.f, 0.f};
#pragma unroll
        for (int r = 0; r < 16; r++) {
            float4 v = *(const float4*)&s1[r][d4 * 4];
            acc.x = fmaf(w2[r], v.x, acc.x);
            acc.y = fmaf(w2[r], v.y, acc.y);
            acc.z = fmaf(w2[r], v.z, acc.z);
            acc.w = fmaf(w2[r], v.w, acc.w);
        }
        split4(acc, wallh, walll, (2048 + n) * 512 + (d0 >> 2) + d4);
    }
}

// ===========================================================================
// CHUNKED GLA SCAN (exact algebra; fp32).  Chunk length CH=64.
// ===========================================================================

// ---------- Phase A ----------------------------------------------------------
#define PHA_SMEM (16384 * 4)
__global__ __launch_bounds__(256)
void gla_pha(const float* __restrict__ k, const float* __restrict__ kg,
             const float* __restrict__ v, float* __restrict__ a_g,
             float* __restrict__ U_g)
{
    extern __shared__ float sa[];
    float* lam = sa;                 // [64][64]
    float* kh  = sa + 4096;          // [64][64]
    float* vsm = sa + 8192;          // [64][128]

    const int blk = blockIdx.x;
    const int c   = blk & (NCK - 1);
    const int bh  = blk >> 5;
    const int b   = bh >> 4, h = bh & 15;
    const int t0  = c * CH;
    const int tid = threadIdx.x;

    const float* kb = k  + (size_t)b * SEQ * PS + h * DK;
    const float* gb = kg + (size_t)b * SEQ * PS + h * DK;
    const float* vb = v  + (size_t)b * SEQ * PS + h * DV;
    float* ag = a_g + ((size_t)bh * SEQ + t0) * DK;
    float* Ug = U_g + (size_t)blk * (DK * DV);

    for (int e = tid; e < CH * DK; e += 256) {
        int t = e >> 6, i = e & 63;
        float x = gb[(size_t)(t0 + t) * PS + i];
        float ls = fminf(x, 0.f) - log1pf(__expf(-fabsf(x)));
        lam[t * DK + i] = __expf(ls * INV_NORM);
    }
    for (int e = tid; e < CH * (DV / 4); e += 256) {
        int t = e >> 5, j4 = e & 31;
        *(float4*)&vsm[t * DV + j4 * 4] =
            *(const float4*)&vb[(size_t)(t0 + t) * PS + j4 * 4];
    }
    __syncthreads();

    if (tid < DK) {
        const int i = tid;
        float acc = 1.f;
        for (int t = 0; t < CH; t++) {
            acc *= lam[t * DK + i];
            ag[(size_t)t * DK + i] = acc;
        }
        float w = 1.f;
        for (int t = CH - 1; t >= 0; t--) {
            kh[t * DK + i] = kb[(size_t)(t0 + t) * PS + i] * w;
            w *= lam[t * DK + i];
        }
    }
    __syncthreads();

    {
        const int i0 = (tid >> 5) * 8;
        const int j0 = (tid & 31) * 4;
        float acc[8][4];
#pragma unroll
        for (int ii = 0; ii < 8; ii++)
#pragma unroll
            for (int jj = 0; jj < 4; jj++) acc[ii][jj] = 0.f;

        for (int s = 0; s < CH; s++) {
            float4 va = *(const float4*)&vsm[s * DV + j0];
            float kv[8];
            *(float4*)&kv[0] = *(const float4*)&kh[s * DK + i0];
            *(float4*)&kv[4] = *(const float4*)&kh[s * DK + i0 + 4];
#pragma unroll
            for (int ii = 0; ii < 8; ii++) {
                acc[ii][0] = fmaf(kv[ii], va.x, acc[ii][0]);
                acc[ii][1] = fmaf(kv[ii], va.y, acc[ii][1]);
                acc[ii][2] = fmaf(kv[ii], va.z, acc[ii][2]);
                acc[ii][3] = fmaf(kv[ii], va.w, acc[ii][3]);
            }
        }
#pragma unroll
        for (int ii = 0; ii < 8; ii++) {
            float4 w4 = { acc[ii][0], acc[ii][1], acc[ii][2], acc[ii][3] };
            *(float4*)&Ug[(size_t)(i0 + ii) * DV + j0] = w4;
        }
    }
}

// ---------- Phase B ----------------------------------------------------------
__global__ __launch_bounds__(256)
void gla_phb(const float* __restrict__ a_g, const float* __restrict__ U_g,
             float* __restrict__ Sp_g)
{
    const int bh  = blockIdx.x;
    const int tid = threadIdx.x;
    float S[32];
#pragma unroll
    for (int w = 0; w < 32; w++) S[w] = 0.f;

    for (int c = 0; c < NCK; c++) {
        const float* Ug = U_g + ((size_t)bh * NCK + c) * (DK * DV);
        float* Sg = Sp_g + ((size_t)bh * NCK + c) * (DK * DV);
        const float* a64 = a_g + ((size_t)bh * SEQ + c * CH + CH - 1) * DK;
#pragma unroll
        for (int w = 0; w < 8; w++) {
            int f4 = tid + w * 256;
            int i = f4 >> 5;
            float ai = a64[i];
            float4 u = ((const float4*)Ug)[f4];
            float4 s = *(float4*)&S[w * 4];
            ((float4*)Sg)[f4] = s;
            s.x = fmaf(s.x, ai, u.x);
            s.y = fmaf(s.y, ai, u.y);
            s.z = fmaf(s.z, ai, u.z);
            s.w = fmaf(s.w, ai, u.w);
            *(float4*)&S[w * 4] = s;
        }
    }
}

// ---------- Phase C (register-tiled, FUSED LN+SiLU gate+bf16 split) ----------
#define PHC_SMEM (25088 * 4)
__global__ __launch_bounds__(256)
void gla_phc(const float* __restrict__ q, const float* __restrict__ a_g,
             const float* __restrict__ k, const float* __restrict__ Sp_g,
             const float* __restrict__ v, const float* __restrict__ gp,
             __nv_bfloat16* __restrict__ zh, __nv_bfloat16* __restrict__ zl)
{
    extern __shared__ float sc[];
    float* qt  = sc;            // [64][68]
    float* kT  = sc + 4352;     // [64(i)][68(s)]; Am aliases this after A-stage
    float* Am  = sc + 4352;
    float* vsm = sc + 8704;     // [64][128]
    float* Ssm = sc + 16896;    // [64][128]

    const int blk = blockIdx.x;
    const int c   = blk & (NCK - 1);
    const int bh  = blk >> 5;
    const int b   = bh >> 4, h = bh & 15;
    const int t0  = c * CH;
    const int tid = threadIdx.x;

    const float* qb = q + (size_t)b * SEQ * PS + h * DK;
    const float* kb = k + (size_t)b * SEQ * PS + h * DK;
    const float* vb = v + (size_t)b * SEQ * PS + h * DV;
    const float* gpb = gp + (size_t)b * SEQ * PS + h * DV;
    const float* ag = a_g + ((size_t)bh * SEQ + t0) * DK;
    const float* Sg = Sp_g + (size_t)blk * (DK * DV);

    for (int e = tid; e < CH * DK; e += 256) {
        int t = e >> 6, i = e & 63;
        float aa = ag[(size_t)t * DK + i];
        qt[t * 68 + i] = qb[(size_t)(t0 + t) * PS + i] * aa;
        kT[i * 68 + t] = kb[(size_t)(t0 + t) * PS + i] / aa;
    }
    for (int e = tid; e < CH * (DV / 4); e += 256) {
        int t = e >> 5, j4 = e & 31;
        *(float4*)&vsm[t * DV + j4 * 4] =
            *(const float4*)&vb[(size_t)(t0 + t) * PS + j4 * 4];
        *(float4*)&Ssm[t * DV + j4 * 4] = ((const float4*)Sg)[e];
    }
    __syncthreads();

    // A = tril(qt @ kT): thread owns 2 t x 8 s (regs across barrier; Am aliases kT)
    {
        const int ta = (tid >> 3) * 2;
        const int s0 = (tid & 7) * 8;
        float acc0[8], acc1[8];
#pragma unroll
        for (int ss = 0; ss < 8; ss++) { acc0[ss] = 0.f; acc1[ss] = 0.f; }
        for (int i = 0; i < DK; i++) {
            float q0 = qt[ta * 68 + i];
            float q1 = qt[(ta + 1) * 68 + i];
            const float* kr = &kT[i * 68 + s0];
            float4 k0 = *(const float4*)&kr[0];
            float4 k1 = *(const float4*)&kr[4];
            float kv[8] = { k0.x, k0.y, k0.z, k0.w, k1.x, k1.y, k1.z, k1.w };
#pragma unroll
            for (int ss = 0; ss < 8; ss++) {
                acc0[ss] = fmaf(q0, kv[ss], acc0[ss]);
                acc1[ss] = fmaf(q1, kv[ss], acc1[ss]);
            }
        }
        __syncthreads();
#pragma unroll
        for (int ss = 0; ss < 8; ss++) {
            int s = s0 + ss;
            Am[ta * 68 + s]       = (s <= ta)     ? acc0[ss] : 0.f;
            Am[(ta + 1) * 68 + s] = (s <= ta + 1) ? acc1[ss] : 0.f;
        }
    }
    __syncthreads();

    // o = A@V + qt@S_pre : thread owns 4 t x 8 j; then fused LN+gate+split.
    {
        const int to = (tid >> 4) * 4;
        const int j0 = (tid & 15) * 8;
        float acc[4][8];
#pragma unroll
        for (int r = 0; r < 4; r++)
#pragma unroll
            for (int jj = 0; jj < 8; jj++) acc[r][jj] = 0.f;

        const int smax = to + 4;
        for (int s = 0; s < smax; s++) {
            float a0 = Am[to * 68 + s];
            float a1 = Am[(to + 1) * 68 + s];
            float a2 = Am[(to + 2) * 68 + s];
            float a3 = Am[(to + 3) * 68 + s];
            const float* vr = &vsm[s * DV + j0];
            float4 v0 = *(const float4*)&vr[0];
            float4 v1 = *(const float4*)&vr[4];
            float vv[8] = { v0.x, v0.y, v0.z, v0.w, v1.x, v1.y, v1.z, v1.w };
#pragma unroll
            for (int jj = 0; jj < 8; jj++) {
                acc[0][jj] = fmaf(a0, vv[jj], acc[0][jj]);
                acc[1][jj] = fmaf(a1, vv[jj], acc[1][jj]);
                acc[2][jj] = fmaf(a2, vv[jj], acc[2][jj]);
                acc[3][jj] = fmaf(a3, vv[jj], acc[3][jj]);
            }
        }
        for (int i = 0; i < DK; i++) {
            float q0 = qt[to * 68 + i];
            float q1 = qt[(to + 1) * 68 + i];
            float q2 = qt[(to + 2) * 68 + i];
            float q3 = qt[(to + 3) * 68 + i];
            const float* sr = &Ssm[i * DV + j0];
            float4 s0v = *(const float4*)&sr[0];
            float4 s1v = *(const float4*)&sr[4];
            float sv[8] = { s0v.x, s0v.y, s0v.z, s0v.w, s1v.x, s1v.y, s1v.z, s1v.w };
#pragma unroll
            for (int jj = 0; jj < 8; jj++) {
                acc[0][jj] = fmaf(q0, sv[jj], acc[0][jj]);
                acc[1][jj] = fmaf(q1, sv[jj], acc[1][jj]);
                acc[2][jj] = fmaf(q2, sv[jj], acc[2][jj]);
                acc[3][jj] = fmaf(q3, sv[jj], acc[3][jj]);
            }
        }

#pragma unroll
        for (int r = 0; r < 4; r++) {
            float s = 0.f;
#pragma unroll
            for (int jj = 0; jj < 8; jj++) s += acc[r][jj];
            s += __shfl_xor_sync(0xffffffffu, s, 8);
            s += __shfl_xor_sync(0xffffffffu, s, 4);
            s += __shfl_xor_sync(0xffffffffu, s, 2);
            s += __shfl_xor_sync(0xffffffffu, s, 1);
            float mu = s * (1.f / 128.f);

            float dx[8], vs = 0.f;
#pragma unroll
            for (int jj = 0; jj < 8; jj++) { dx[jj] = acc[r][jj] - mu; vs += dx[jj] * dx[jj]; }
            vs += __shfl_xor_sync(0xffffffffu, vs, 8);
            vs += __shfl_xor_sync(0xffffffffu, vs, 4);
            vs += __shfl_xor_sync(0xffffffffu, vs, 2);
            vs += __shfl_xor_sync(0xffffffffu, vs, 1);
            float inv = rsqrtf(vs * (1.f / 128.f) + 1e-5f);

            const int t = t0 + to + r;
            const float* gr = gpb + (size_t)t * PS + j0;
            float4 g0 = *(const float4*)&gr[0];
            float4 g1 = *(const float4*)&gr[4];
            float gv[8] = { g0.x, g0.y, g0.z, g0.w, g1.x, g1.y, g1.z, g1.w };
            float z[8];
#pragma unroll
            for (int jj = 0; jj < 8; jj++)
                z[jj] = (gv[jj] / (1.f + __expf(-gv[jj]))) * (dx[jj] * inv);

            const int m = b * SEQ + t;
            const int zi = (m * DMODEL + h * DV + j0) >> 2;
            float4 z0 = { z[0], z[1], z[2], z[3] };
            float4 z1 = { z[4], z[5], z[6], z[7] };
            split4(z0, zh, zl, zi);
            split4(z1, zh, zl, zi + 1);
        }
    }
}

// ---------------------------------------------------------------------------
// Host: tensor-map construction (driver entry point via cudart; no -lcuda)
// ---------------------------------------------------------------------------
typedef CUresult (*PFN_tmEncode)(
    CUtensorMap*, CUtensorMapDataType, cuuint32_t, void*,
    const cuuint64_t*, const cuuint64_t*, const cuuint32_t*, const cuuint32_t*,
    CUtensorMapInterleave, CUtensorMapSwizzle, CUtensorMapL2promotion,
    CUtensorMapFloatOOBfill);

static void make_map(PFN_tmEncode fn, CUtensorMap* m, void* ptr, unsigned long long rows)
{
    cuuint64_t dims[2]    = { 2048ull, rows };
    cuuint64_t strides[1] = { 4096ull };          // row stride bytes (K=2048 bf16)
    cuuint32_t box[2]     = { 32u, 256u };        // 32 elems (64B) x 256 rows
    cuuint32_t es[2]      = { 1u, 1u };
    fn(m, CU_TENSOR_MAP_DATA_TYPE_UINT16, 2, ptr, dims, strides, box, es,
       CU_TENSOR_MAP_INTERLEAVE_NONE, CU_TENSOR_MAP_SWIZZLE_64B,
       CU_TENSOR_MAP_L2_PROMOTION_L2_128B, CU_TENSOR_MAP_FLOAT_OOB_FILL_NONE);
}

// ---------------------------------------------------------------------------
extern "C" void kernel_launch(void* const* d_in, const int* in_sizes, int n_in,
                              void* d_out, int out_size)
{
    const float* x    = (const float*)d_in[0];
    const float* Wq   = (const float*)d_in[1];
    const float* Wk   = (const float*)d_in[2];
    const float* Wkg1 = (const float*)d_in[3];
    const float* Wkg2 = (const float*)d_in[4];
    const float* bkg2 = (const float*)d_in[5];
    const float* Wv   = (const float*)d_in[6];
    const float* Wg   = (const float*)d_in[7];
    const float* bg   = (const float*)d_in[8];
    const float* Wo   = (const float*)d_in[9];
    float* out = (float*)d_out;

    float *proj, *ad, *Ud, *Sp, *ball;
    cudaGetSymbolAddress((void**)&proj, g_proj);
    cudaGetSymbolAddress((void**)&ad,   g_a);
    cudaGetSymbolAddress((void**)&Ud,   g_U);
    cudaGetSymbolAddress((void**)&Sp,   g_Sp);
    cudaGetSymbolAddress((void**)&ball, g_ball);

    __nv_bfloat16 *xh, *xl, *zh, *zl;
    __nv_bfloat16 *wallh, *walll, *woh, *wol;
    cudaGetSymbolAddress((void**)&xh,    g_xh);    cudaGetSymbolAddress((void**)&xl,    g_xl);
    cudaGetSymbolAddress((void**)&zh,    g_zh);    cudaGetSymbolAddress((void**)&zl,    g_zl);
    cudaGetSymbolAddress((void**)&wallh, g_wallh); cudaGetSymbolAddress((void**)&walll, g_walll);
    cudaGetSymbolAddress((void**)&woh,   g_woh);   cudaGetSymbolAddress((void**)&wol,   g_wol);

    // tensor maps (rebuilt every call; host-side pure function, capture-safe)
    PFN_tmEncode tmEncode = nullptr;
    cudaDriverEntryPointQueryResult qres;
    cudaGetDriverEntryPoint("cuTensorMapEncodeTiled", (void**)&tmEncode,
                            cudaEnableDefault, &qres);
    CUtensorMap tm_xh, tm_xl, tm_wh, tm_wl, tm_zh, tm_zl, tm_oh, tm_ol;
    make_map(tmEncode, &tm_xh, xh, MTOK);
    make_map(tmEncode, &tm_xl, xl, MTOK);
    make_map(tmEncode, &tm_wh, wallh, PS);
    make_map(tmEncode, &tm_wl, walll, PS);
    make_map(tmEncode, &tm_zh, zh, MTOK);
    make_map(tmEncode, &tm_zl, zl, MTOK);
    make_map(tmEncode, &tm_oh, woh, DMODEL);
    make_map(tmEncode, &tm_ol, wol, DMODEL);

    cudaFuncSetAttribute(gemm3, cudaFuncAttributeMaxDynamicSharedMemorySize, GEMM_DSM);
    cudaFuncSetAttribute(gla_pha, cudaFuncAttributeMaxDynamicSharedMemorySize, PHA_SMEM);
    cudaFuncSetAttribute(gla_phc, cudaFuncAttributeMaxDynamicSharedMemorySize, PHC_SMEM);

    // x split + bias fill (one launch), weight splits, low-rank weight product
    split32<<<2048 + 28, 256>>>(x, xh, xl, bkg2, bg, ball);
    split_w<<<4096, 256>>>(Wq, Wk, Wv, Wg, Wo, wallh, walll, woh, wol);
    weff_split<<<dim3(16, 4), 256>>>(Wkg1, Wkg2, wallh, walll);

    dim3 blk(GEMM_THREADS);
    dim3 gPROJ(PS / 256, MTOK / 256);      // 28 x 16 = 448 CTAs
    dim3 gOUT (DMODEL / 256, MTOK / 256);  // 8 x 16

    gemm3<<<gPROJ, blk, GEMM_DSM>>>(tm_xh, tm_xl, tm_wh, tm_wl,
                                    xh, xl, wallh, walll, ball, proj, PS, DMODEL, 1.f);

    // chunked scan (q=proj+0, k=+1024, kg=+2048, v=+3072; gp=+5120)
    gla_pha<<<BH * NCK, 256, PHA_SMEM>>>(proj + 1024, proj + 2048, proj + 3072, ad, Ud);
    gla_phb<<<BH, 256>>>(ad, Ud, Sp);
    gla_phc<<<BH * NCK, 256, PHC_SMEM>>>(proj, ad, proj + 1024, Sp, proj + 3072,
                                         proj + 5120, zh, zl);

    gemm3<<<gOUT, blk, GEMM_DSM>>>(tm_zh, tm_zl, tm_oh, tm_ol,
                                   zh, zl, woh, wol, nullptr, out, DMODEL, DMODEL, 1.f);
}